// round 1
// baseline (speedup 1.0000x reference)
#include <cuda_runtime.h>

// Problem constants
#define Bn 4
#define Tn 1024
#define Sn 1024
#define Hn 16
#define Dn 64

// Tiling
#define TQ  32          // queries per block
#define SKT 128         // key/value tile (S direction)
#define NTHREADS 256
#define KV_STRIDE 65    // padded row stride for K/V tile (bank-conflict-free scalar LDS)

#define SMEM_FLOATS (TQ*Dn + SKT*KV_STRIDE + TQ*Sn)
#define SMEM_BYTES  (SMEM_FLOATS * 4)

__global__ __launch_bounds__(NTHREADS, 1)
void attn_fwd_kernel(const float* __restrict__ q,
                     const float* __restrict__ k,
                     const float* __restrict__ v,
                     float* __restrict__ out_attn,
                     float* __restrict__ out_probs) {
    extern __shared__ float smem[];
    float* q_s  = smem;                       // [TQ][Dn]
    float* kv_s = q_s + TQ * Dn;              // [SKT][KV_STRIDE]
    float* lg   = kv_s + SKT * KV_STRIDE;     // [TQ][Sn] logits -> probs

    const int t0   = blockIdx.x * TQ;
    const int h    = blockIdx.y;
    const int b    = blockIdx.z;
    const int tid  = threadIdx.x;
    const int lane = tid & 31;
    const int qg   = tid >> 5;                // warp id: owns queries qg*4 .. qg*4+3

    const float* qbase = q + (((size_t)b * Tn + t0) * Hn + h) * Dn;
    const float* kbase = k + ((size_t)b * Sn * Hn + h) * Dn;
    const float* vbase = v + ((size_t)b * Sn * Hn + h) * Dn;

    // ---- Load Q tile (TQ x Dn), float4 coalesced ----
    #pragma unroll
    for (int u = 0; u < (TQ * Dn / 4) / NTHREADS; u++) {   // 2 iters
        int fid = tid + u * NTHREADS;
        int row = fid >> 4;
        int c   = (fid & 15) << 2;
        float4 val = *(const float4*)(qbase + (size_t)row * Hn * Dn + c);
        *(float4*)(q_s + row * Dn + c) = val;
    }

    // ================= Phase 1: logits = (Q K^T) / sqrt(D) =================
    for (int st = 0; st < Sn / SKT; st++) {
        __syncthreads();   // protect kv_s reuse (and Q visibility on iter 0 via next sync)
        // Load K tile SKT x Dn into padded smem
        #pragma unroll
        for (int u = 0; u < (SKT * Dn / 4) / NTHREADS; u++) {  // 8 iters
            int fid = tid + u * NTHREADS;
            int r = fid >> 4;
            int c = (fid & 15) << 2;
            float4 val = *(const float4*)(kbase + (size_t)(st * SKT + r) * Hn * Dn + c);
            float* dst = kv_s + r * KV_STRIDE + c;
            dst[0] = val.x; dst[1] = val.y; dst[2] = val.z; dst[3] = val.w;
        }
        __syncthreads();

        // 4q x 4k micro-tile per thread; keys = lane + 32e (conflict-free LDS)
        float acc[4][4];
        #pragma unroll
        for (int j = 0; j < 4; j++)
            #pragma unroll
            for (int e = 0; e < 4; e++) acc[j][e] = 0.f;

        #pragma unroll 4
        for (int d = 0; d < Dn; d++) {
            float kv0 = kv_s[(lane      ) * KV_STRIDE + d];
            float kv1 = kv_s[(lane + 32 ) * KV_STRIDE + d];
            float kv2 = kv_s[(lane + 64 ) * KV_STRIDE + d];
            float kv3 = kv_s[(lane + 96 ) * KV_STRIDE + d];
            #pragma unroll
            for (int j = 0; j < 4; j++) {
                float qv = q_s[(qg * 4 + j) * Dn + d];
                acc[j][0] = fmaf(qv, kv0, acc[j][0]);
                acc[j][1] = fmaf(qv, kv1, acc[j][1]);
                acc[j][2] = fmaf(qv, kv2, acc[j][2]);
                acc[j][3] = fmaf(qv, kv3, acc[j][3]);
            }
        }
        #pragma unroll
        for (int j = 0; j < 4; j++) {
            float* lrow = lg + (qg * 4 + j) * Sn + st * SKT;
            #pragma unroll
            for (int e = 0; e < 4; e++)
                lrow[lane + 32 * e] = acc[j][e] * 0.125f;   // 1/sqrt(64)
        }
    }

    // ================= Phase 2: softmax + probs write (warp-private rows) =================
    #pragma unroll
    for (int j = 0; j < 4; j++) {
        const int row = qg * 4 + j;
        float* lrow = lg + row * Sn;

        float m = -1e30f;
        for (int s = lane; s < Sn; s += 32) m = fmaxf(m, lrow[s]);
        #pragma unroll
        for (int o = 16; o > 0; o >>= 1) m = fmaxf(m, __shfl_xor_sync(0xffffffffu, m, o));

        float sum = 0.f;
        for (int s = lane; s < Sn; s += 32) {
            float e = __expf(lrow[s] - m);
            lrow[s] = e;
            sum += e;
        }
        #pragma unroll
        for (int o = 16; o > 0; o >>= 1) sum += __shfl_xor_sync(0xffffffffu, sum, o);
        const float inv = 1.f / sum;

        float* prow = out_probs + (((size_t)b * Tn + (t0 + row)) * Hn + h) * Sn;
        for (int s = lane; s < Sn; s += 32) {
            float p = lrow[s] * inv;
            lrow[s] = p;
            prow[s] = p;        // coalesced 128B stores
        }
    }

    // ================= Phase 3: attn = P V =================
    float oacc[4][2];
    #pragma unroll
    for (int j = 0; j < 4; j++) { oacc[j][0] = 0.f; oacc[j][1] = 0.f; }

    for (int st = 0; st < Sn / SKT; st++) {
        __syncthreads();   // prev kv_s readers done (also orders softmax lg writes before PV float2 reads)
        #pragma unroll
        for (int u = 0; u < (SKT * Dn / 4) / NTHREADS; u++) {
            int fid = tid + u * NTHREADS;
            int r = fid >> 4;
            int c = (fid & 15) << 2;
            float4 val = *(const float4*)(vbase + (size_t)(st * SKT + r) * Hn * Dn + c);
            float* dst = kv_s + r * KV_STRIDE + c;
            dst[0] = val.x; dst[1] = val.y; dst[2] = val.z; dst[3] = val.w;
        }
        __syncthreads();

        #pragma unroll 8
        for (int s = 0; s < SKT; s += 2) {
            float v00 = kv_s[ s      * KV_STRIDE + lane      ];
            float v01 = kv_s[ s      * KV_STRIDE + lane + 32 ];
            float v10 = kv_s[(s + 1) * KV_STRIDE + lane      ];
            float v11 = kv_s[(s + 1) * KV_STRIDE + lane + 32 ];
            #pragma unroll
            for (int j = 0; j < 4; j++) {
                float2 p = *(const float2*)(lg + (qg * 4 + j) * Sn + st * SKT + s);
                oacc[j][0] = fmaf(p.x, v00, oacc[j][0]);
                oacc[j][0] = fmaf(p.y, v10, oacc[j][0]);
                oacc[j][1] = fmaf(p.x, v01, oacc[j][1]);
                oacc[j][1] = fmaf(p.y, v11, oacc[j][1]);
            }
        }
    }

    #pragma unroll
    for (int j = 0; j < 4; j++) {
        float* orow = out_attn + (((size_t)b * Tn + (t0 + qg * 4 + j)) * Hn + h) * Dn;
        orow[lane]      = oacc[j][0];
        orow[lane + 32] = oacc[j][1];
    }
}

extern "C" void kernel_launch(void* const* d_in, const int* in_sizes, int n_in,
                              void* d_out, int out_size) {
    const float* q = (const float*)d_in[0];
    const float* k = (const float*)d_in[1];
    const float* v = (const float*)d_in[2];

    float* out_attn  = (float*)d_out;                                  // (B,T,H,D)
    float* out_probs = (float*)d_out + (size_t)Bn * Tn * Hn * Dn;      // (B,T,H,S)

    cudaFuncSetAttribute(attn_fwd_kernel,
                         cudaFuncAttributeMaxDynamicSharedMemorySize, SMEM_BYTES);

    dim3 grid(Tn / TQ, Hn, Bn);   // t-tile fastest -> same (b,h) CTAs adjacent for K/V L2 reuse
    attn_fwd_kernel<<<grid, NTHREADS, SMEM_BYTES>>>(q, k, v, out_attn, out_probs);
}

// round 2
// speedup vs baseline: 1.0027x; 1.0027x over previous
#include <cuda_runtime.h>

// Problem constants
#define Bn 4
#define Tn 1024
#define Sn 1024
#define Hn 16
#define Dn 64

// Tiling
#define TQ  32          // queries per block
#define SKT 128         // key/value tile (S direction)
#define NTHREADS 256
#define KV_STRIDE 65    // padded row stride for K/V tile (bank-conflict-free scalar LDS)

#define SMEM_FLOATS (TQ*Dn + SKT*KV_STRIDE + TQ*Sn)
#define SMEM_BYTES  (SMEM_FLOATS * 4)

__global__ __launch_bounds__(NTHREADS, 1)
void attn_fwd_kernel(const float* __restrict__ q,
                     const float* __restrict__ k,
                     const float* __restrict__ v,
                     float* __restrict__ out_attn,
                     float* __restrict__ out_probs) {
    extern __shared__ float smem[];
    float* q_s  = smem;                       // [TQ][Dn]
    float* kv_s = q_s + TQ * Dn;              // [SKT][KV_STRIDE]
    float* lg   = kv_s + SKT * KV_STRIDE;     // [TQ][Sn] logits -> probs

    const int t0   = blockIdx.x * TQ;
    const int h    = blockIdx.y;
    const int b    = blockIdx.z;
    const int tid  = threadIdx.x;
    const int lane = tid & 31;
    const int qg   = tid >> 5;                // warp id: owns queries qg*4 .. qg*4+3

    const float* qbase = q + (((size_t)b * Tn + t0) * Hn + h) * Dn;
    const float* kbase = k + ((size_t)b * Sn * Hn + h) * Dn;
    const float* vbase = v + ((size_t)b * Sn * Hn + h) * Dn;

    // ---- Load Q tile (TQ x Dn), float4 coalesced ----
    #pragma unroll
    for (int u = 0; u < (TQ * Dn / 4) / NTHREADS; u++) {   // 2 iters
        int fid = tid + u * NTHREADS;
        int row = fid >> 4;
        int c   = (fid & 15) << 2;
        float4 val = *(const float4*)(qbase + (size_t)row * Hn * Dn + c);
        *(float4*)(q_s + row * Dn + c) = val;
    }

    // ================= Phase 1: logits = (Q K^T) / sqrt(D) =================
    for (int st = 0; st < Sn / SKT; st++) {
        __syncthreads();   // protect kv_s reuse (and Q visibility on iter 0 via next sync)
        // Load K tile SKT x Dn into padded smem
        #pragma unroll
        for (int u = 0; u < (SKT * Dn / 4) / NTHREADS; u++) {  // 8 iters
            int fid = tid + u * NTHREADS;
            int r = fid >> 4;
            int c = (fid & 15) << 2;
            float4 val = *(const float4*)(kbase + (size_t)(st * SKT + r) * Hn * Dn + c);
            float* dst = kv_s + r * KV_STRIDE + c;
            dst[0] = val.x; dst[1] = val.y; dst[2] = val.z; dst[3] = val.w;
        }
        __syncthreads();

        // 4q x 4k micro-tile per thread; keys = lane + 32e (conflict-free LDS)
        float acc[4][4];
        #pragma unroll
        for (int j = 0; j < 4; j++)
            #pragma unroll
            for (int e = 0; e < 4; e++) acc[j][e] = 0.f;

        #pragma unroll 4
        for (int d = 0; d < Dn; d++) {
            float kv0 = kv_s[(lane      ) * KV_STRIDE + d];
            float kv1 = kv_s[(lane + 32 ) * KV_STRIDE + d];
            float kv2 = kv_s[(lane + 64 ) * KV_STRIDE + d];
            float kv3 = kv_s[(lane + 96 ) * KV_STRIDE + d];
            #pragma unroll
            for (int j = 0; j < 4; j++) {
                float qv = q_s[(qg * 4 + j) * Dn + d];
                acc[j][0] = fmaf(qv, kv0, acc[j][0]);
                acc[j][1] = fmaf(qv, kv1, acc[j][1]);
                acc[j][2] = fmaf(qv, kv2, acc[j][2]);
                acc[j][3] = fmaf(qv, kv3, acc[j][3]);
            }
        }
        #pragma unroll
        for (int j = 0; j < 4; j++) {
            float* lrow = lg + (qg * 4 + j) * Sn + st * SKT;
            #pragma unroll
            for (int e = 0; e < 4; e++)
                lrow[lane + 32 * e] = acc[j][e] * 0.125f;   // 1/sqrt(64)
        }
    }

    // ================= Phase 2: softmax + probs write (warp-private rows) =================
    #pragma unroll
    for (int j = 0; j < 4; j++) {
        const int row = qg * 4 + j;
        float* lrow = lg + row * Sn;

        float m = -1e30f;
        for (int s = lane; s < Sn; s += 32) m = fmaxf(m, lrow[s]);
        #pragma unroll
        for (int o = 16; o > 0; o >>= 1) m = fmaxf(m, __shfl_xor_sync(0xffffffffu, m, o));

        float sum = 0.f;
        for (int s = lane; s < Sn; s += 32) {
            float e = __expf(lrow[s] - m);
            lrow[s] = e;
            sum += e;
        }
        #pragma unroll
        for (int o = 16; o > 0; o >>= 1) sum += __shfl_xor_sync(0xffffffffu, sum, o);
        const float inv = 1.f / sum;

        float* prow = out_probs + (((size_t)b * Tn + (t0 + row)) * Hn + h) * Sn;
        for (int s = lane; s < Sn; s += 32) {
            float p = lrow[s] * inv;
            lrow[s] = p;
            prow[s] = p;        // coalesced 128B stores
        }
    }

    // ================= Phase 3: attn = P V =================
    float oacc[4][2];
    #pragma unroll
    for (int j = 0; j < 4; j++) { oacc[j][0] = 0.f; oacc[j][1] = 0.f; }

    for (int st = 0; st < Sn / SKT; st++) {
        __syncthreads();   // prev kv_s readers done (also orders softmax lg writes before PV float2 reads)
        #pragma unroll
        for (int u = 0; u < (SKT * Dn / 4) / NTHREADS; u++) {
            int fid = tid + u * NTHREADS;
            int r = fid >> 4;
            int c = (fid & 15) << 2;
            float4 val = *(const float4*)(vbase + (size_t)(st * SKT + r) * Hn * Dn + c);
            float* dst = kv_s + r * KV_STRIDE + c;
            dst[0] = val.x; dst[1] = val.y; dst[2] = val.z; dst[3] = val.w;
        }
        __syncthreads();

        #pragma unroll 8
        for (int s = 0; s < SKT; s += 2) {
            float v00 = kv_s[ s      * KV_STRIDE + lane      ];
            float v01 = kv_s[ s      * KV_STRIDE + lane + 32 ];
            float v10 = kv_s[(s + 1) * KV_STRIDE + lane      ];
            float v11 = kv_s[(s + 1) * KV_STRIDE + lane + 32 ];
            #pragma unroll
            for (int j = 0; j < 4; j++) {
                float2 p = *(const float2*)(lg + (qg * 4 + j) * Sn + st * SKT + s);
                oacc[j][0] = fmaf(p.x, v00, oacc[j][0]);
                oacc[j][0] = fmaf(p.y, v10, oacc[j][0]);
                oacc[j][1] = fmaf(p.x, v01, oacc[j][1]);
                oacc[j][1] = fmaf(p.y, v11, oacc[j][1]);
            }
        }
    }

    #pragma unroll
    for (int j = 0; j < 4; j++) {
        float* orow = out_attn + (((size_t)b * Tn + (t0 + qg * 4 + j)) * Hn + h) * Dn;
        orow[lane]      = oacc[j][0];
        orow[lane + 32] = oacc[j][1];
    }
}

extern "C" void kernel_launch(void* const* d_in, const int* in_sizes, int n_in,
                              void* d_out, int out_size) {
    const float* q = (const float*)d_in[0];
    const float* k = (const float*)d_in[1];
    const float* v = (const float*)d_in[2];

    float* out_attn  = (float*)d_out;                                  // (B,T,H,D)
    float* out_probs = (float*)d_out + (size_t)Bn * Tn * Hn * Dn;      // (B,T,H,S)

    cudaFuncSetAttribute(attn_fwd_kernel,
                         cudaFuncAttributeMaxDynamicSharedMemorySize, SMEM_BYTES);

    dim3 grid(Tn / TQ, Hn, Bn);   // t-tile fastest -> same (b,h) CTAs adjacent for K/V L2 reuse
    attn_fwd_kernel<<<grid, NTHREADS, SMEM_BYTES>>>(q, k, v, out_attn, out_probs);
}

// round 4
// speedup vs baseline: 1.7737x; 1.7689x over previous
#include <cuda_runtime.h>
#include <cuda_bf16.h>
#include <cstdint>

#define Bn 4
#define Tn 1024
#define Sn 1024
#define Hn 16
#define Dn 64
#define RS (Hn*Dn)           // 1024 floats: stride between consecutive t (or s) rows
#define MQ 64                // queries per CTA
#define NKC 128              // keys per chunk
#define NCH (Sn/NKC)         // 8

// smem byte offsets (each K/V tile: 128 rows x 64 bf16 = 128B/row, SW128 swizzled)
#define SM_KH 0
#define SM_KL 16384
#define SM_VH 32768
#define SM_VL 49152
#define SM_STG 65536
#define STGP 132             // stage pitch in floats (avoid bank conflicts)
#define SMEM_TOTAL (SM_STG + MQ*STGP*4)   // 99328 bytes

// ---------------- PTX wrappers ----------------
__device__ __forceinline__ uint32_t smem_u32(const void* p) {
    uint32_t a;
    asm("{ .reg .u64 t; cvta.to.shared.u64 t, %1; cvt.u32.u64 %0, t; }" : "=r"(a) : "l"(p));
    return a;
}

__device__ __forceinline__ void ldsm_x4(uint32_t* r, uint32_t addr) {
    asm volatile("ldmatrix.sync.aligned.m8n8.x4.shared.b16 {%0,%1,%2,%3}, [%4];"
        : "=r"(r[0]), "=r"(r[1]), "=r"(r[2]), "=r"(r[3]) : "r"(addr));
}
__device__ __forceinline__ void ldsm_x4_t(uint32_t* r, uint32_t addr) {
    asm volatile("ldmatrix.sync.aligned.m8n8.x4.trans.shared.b16 {%0,%1,%2,%3}, [%4];"
        : "=r"(r[0]), "=r"(r[1]), "=r"(r[2]), "=r"(r[3]) : "r"(addr));
}

__device__ __forceinline__ void mma_bf16(float* c, const uint32_t* a, uint32_t b0, uint32_t b1) {
    asm volatile("mma.sync.aligned.m16n8k16.row.col.f32.bf16.bf16.f32 "
        "{%0,%1,%2,%3}, {%4,%5,%6,%7}, {%8,%9}, {%0,%1,%2,%3};"
        : "+f"(c[0]), "+f"(c[1]), "+f"(c[2]), "+f"(c[3])
        : "r"(a[0]), "r"(a[1]), "r"(a[2]), "r"(a[3]), "r"(b0), "r"(b1));
}

// split (a,b) fp32 pair into packed bf16x2 hi and lo (error-compensation split)
__device__ __forceinline__ void split2(float a, float b, uint32_t& hi, uint32_t& lo) {
    __nv_bfloat16 ah = __float2bfloat16(a), bh = __float2bfloat16(b);
    float ar = a - __bfloat162float(ah), br = b - __bfloat162float(bh);
    __nv_bfloat16 al = __float2bfloat16(ar), bl = __float2bfloat16(br);
    hi = ((uint32_t)__bfloat16_as_ushort(bh) << 16) | __bfloat16_as_ushort(ah);
    lo = ((uint32_t)__bfloat16_as_ushort(bl) << 16) | __bfloat16_as_ushort(al);
}

// convert one 128x64 fp32 gmem tile -> bf16 hi/lo smem tiles (128B rows, SW128 swizzle)
__device__ __forceinline__ void conv_tile(char* sm, int hioff, int looff,
                                          const float* g, int tid) {
    #pragma unroll
    for (int u = 0; u < 16; u++) {
        int fid = tid + u * 128;
        int r = fid >> 4, c4 = fid & 15;
        float4 x = *(const float4*)(g + (size_t)r * RS + c4 * 4);
        uint32_t h0, l0, h1, l1;
        split2(x.x, x.y, h0, l0);
        split2(x.z, x.w, h1, l1);
        uint32_t off = (uint32_t)(r * 128 + c4 * 8);
        uint32_t so = off ^ ((uint32_t)(r & 7) << 4);
        *(uint2*)(sm + hioff + so) = make_uint2(h0, h1);
        *(uint2*)(sm + looff + so) = make_uint2(l0, l1);
    }
}

__global__ __launch_bounds__(128, 2)
void attn_hmma_kernel(const float* __restrict__ q, const float* __restrict__ k,
                      const float* __restrict__ v,
                      float* __restrict__ out_attn, float* __restrict__ out_probs) {
    extern __shared__ char sm[];
    const uint32_t smb = smem_u32(sm);
    const int tid = threadIdx.x, lane = tid & 31, w = tid >> 5;
    const int t0 = blockIdx.x * MQ, h = blockIdx.y, b = blockIdx.z;
    const int g = lane >> 2, t = lane & 3;
    const int row0 = t0 + w * 16;

    const float* kb = k + ((size_t)b * Sn * Hn + h) * Dn;
    const float* vb = v + ((size_t)b * Sn * Hn + h) * Dn;

    // ---- Q fragments (hi/lo, scaled by 1/sqrt(D)=1/8 folded fully into Q) ----
    uint32_t qh[4][4], ql[4][4];
    {
        const float* qr0 = q + (((size_t)b * Tn + row0 + g) * Hn + h) * Dn;
        const float* qr1 = qr0 + 8 * RS;
        #pragma unroll
        for (int ks = 0; ks < 4; ks++) {
            float2 f0 = *(const float2*)(qr0 + ks * 16 + 2 * t);
            float2 f1 = *(const float2*)(qr1 + ks * 16 + 2 * t);
            float2 f2 = *(const float2*)(qr0 + ks * 16 + 2 * t + 8);
            float2 f3 = *(const float2*)(qr1 + ks * 16 + 2 * t + 8);
            split2(f0.x * 0.125f, f0.y * 0.125f, qh[ks][0], ql[ks][0]);
            split2(f1.x * 0.125f, f1.y * 0.125f, qh[ks][1], ql[ks][1]);
            split2(f2.x * 0.125f, f2.y * 0.125f, qh[ks][2], ql[ks][2]);
            split2(f3.x * 0.125f, f3.y * 0.125f, qh[ks][3], ql[ks][3]);
        }
    }

    // lane-constant ldmatrix address components (shared by K and V patterns)
    const uint32_t rowoff = ((lane >> 4) & 1) * 8 + (lane & 7);
    const uint32_t colsel = ((lane >> 3) & 1) * 16;
    const uint32_t lbase = rowoff * 128 + colsel;
    const uint32_t lxor = (rowoff & 7) << 4;
    const uint32_t kh_b = smb + SM_KH, kl_b = smb + SM_KL;
    const uint32_t vh_b = smb + SM_VH, vl_b = smb + SM_VL;

    float sumA = 0.f, sumB = 0.f;

    // ================= Pass A: row sums =================
    for (int c = 0; c < NCH; c++) {
        __syncthreads();
        conv_tile(sm, SM_KH, SM_KL, kb + (size_t)c * NKC * RS, tid);
        __syncthreads();

        float S[16][4];
        #pragma unroll
        for (int i = 0; i < 16; i++) { S[i][0] = 0.f; S[i][1] = 0.f; S[i][2] = 0.f; S[i][3] = 0.f; }

        #pragma unroll
        for (int ks = 0; ks < 4; ks++) {
            #pragma unroll
            for (int j = 0; j < 8; j++) {
                uint32_t bh[4], bl[4];
                ldsm_x4(bh, (kh_b + j * 2048 + ks * 32 + lbase) ^ lxor);
                ldsm_x4(bl, (kl_b + j * 2048 + ks * 32 + lbase) ^ lxor);
                mma_bf16(S[2 * j],     qh[ks], bh[0], bh[1]);
                mma_bf16(S[2 * j],     qh[ks], bl[0], bl[1]);
                mma_bf16(S[2 * j],     ql[ks], bh[0], bh[1]);
                mma_bf16(S[2 * j + 1], qh[ks], bh[2], bh[3]);
                mma_bf16(S[2 * j + 1], qh[ks], bl[2], bl[3]);
                mma_bf16(S[2 * j + 1], ql[ks], bh[2], bh[3]);
            }
        }
        #pragma unroll
        for (int i = 0; i < 16; i++) {
            sumA += __expf(S[i][0]) + __expf(S[i][1]);
            sumB += __expf(S[i][2]) + __expf(S[i][3]);
        }
    }
    sumA += __shfl_xor_sync(0xffffffffu, sumA, 1);
    sumA += __shfl_xor_sync(0xffffffffu, sumA, 2);
    sumB += __shfl_xor_sync(0xffffffffu, sumB, 1);
    sumB += __shfl_xor_sync(0xffffffffu, sumB, 2);
    const float invA = 1.f / sumA, invB = 1.f / sumB;

    // ================= Pass B: probs + PV =================
    float O[8][4];
    #pragma unroll
    for (int i = 0; i < 8; i++) { O[i][0] = 0.f; O[i][1] = 0.f; O[i][2] = 0.f; O[i][3] = 0.f; }

    float* stg = (float*)(sm + SM_STG);

    for (int c = 0; c < NCH; c++) {
        __syncthreads();
        conv_tile(sm, SM_KH, SM_KL, kb + (size_t)c * NKC * RS, tid);
        conv_tile(sm, SM_VH, SM_VL, vb + (size_t)c * NKC * RS, tid);
        __syncthreads();

        float S[16][4];
        #pragma unroll
        for (int i = 0; i < 16; i++) { S[i][0] = 0.f; S[i][1] = 0.f; S[i][2] = 0.f; S[i][3] = 0.f; }

        #pragma unroll
        for (int ks = 0; ks < 4; ks++) {
            #pragma unroll
            for (int j = 0; j < 8; j++) {
                uint32_t bh[4], bl[4];
                ldsm_x4(bh, (kh_b + j * 2048 + ks * 32 + lbase) ^ lxor);
                ldsm_x4(bl, (kl_b + j * 2048 + ks * 32 + lbase) ^ lxor);
                mma_bf16(S[2 * j],     qh[ks], bh[0], bh[1]);
                mma_bf16(S[2 * j],     qh[ks], bl[0], bl[1]);
                mma_bf16(S[2 * j],     ql[ks], bh[0], bh[1]);
                mma_bf16(S[2 * j + 1], qh[ks], bh[2], bh[3]);
                mma_bf16(S[2 * j + 1], qh[ks], bl[2], bl[3]);
                mma_bf16(S[2 * j + 1], ql[ks], bh[2], bh[3]);
            }
        }

        // exp -> E (bf16 hi/lo frags for PV) + normalized probs into stage
        uint32_t eh[16][2], el[16][2];
        #pragma unroll
        for (int i = 0; i < 16; i++) {
            float e0 = __expf(S[i][0]), e1 = __expf(S[i][1]);
            float e2 = __expf(S[i][2]), e3 = __expf(S[i][3]);
            split2(e0, e1, eh[i][0], el[i][0]);
            split2(e2, e3, eh[i][1], el[i][1]);
            *(float2*)(stg + (w * 16 + g) * STGP + i * 8 + 2 * t)     = make_float2(e0 * invA, e1 * invA);
            *(float2*)(stg + (w * 16 + g + 8) * STGP + i * 8 + 2 * t) = make_float2(e2 * invB, e3 * invB);
        }

        // PV: A frags from E registers, B frags via ldmatrix.trans on V
        #pragma unroll
        for (int ks = 0; ks < 8; ks++) {
            uint32_t ah[4] = { eh[2 * ks][0], eh[2 * ks][1], eh[2 * ks + 1][0], eh[2 * ks + 1][1] };
            uint32_t al[4] = { el[2 * ks][0], el[2 * ks][1], el[2 * ks + 1][0], el[2 * ks + 1][1] };
            #pragma unroll
            for (int p = 0; p < 4; p++) {
                uint32_t bh[4], bl[4];
                ldsm_x4_t(bh, (vh_b + ks * 2048 + p * 32 + lbase) ^ lxor);
                ldsm_x4_t(bl, (vl_b + ks * 2048 + p * 32 + lbase) ^ lxor);
                mma_bf16(O[2 * p],     ah, bh[0], bh[2]);
                mma_bf16(O[2 * p],     ah, bl[0], bl[2]);
                mma_bf16(O[2 * p],     al, bh[0], bh[2]);
                mma_bf16(O[2 * p + 1], ah, bh[1], bh[3]);
                mma_bf16(O[2 * p + 1], ah, bl[1], bl[3]);
                mma_bf16(O[2 * p + 1], al, bh[1], bh[3]);
            }
        }

        __syncthreads();
        // coalesced probs store from stage
        #pragma unroll
        for (int u = 0; u < 16; u++) {
            int fid = tid + u * 128;
            int r = fid >> 5, c4 = fid & 31;
            float4 val = *(const float4*)(stg + r * STGP + c4 * 4);
            *(float4*)(out_probs + (((size_t)b * Tn + t0 + r) * Hn + h) * Sn + c * 128 + c4 * 4) = val;
        }
    }

    // ================= attn output (scaled by 1/rowsum) =================
    float* oar0 = out_attn + (((size_t)b * Tn + row0 + g) * Hn + h) * Dn;
    float* oar1 = oar0 + 8 * RS;
    #pragma unroll
    for (int nd = 0; nd < 8; nd++) {
        *(float2*)(oar0 + nd * 8 + 2 * t) = make_float2(O[nd][0] * invA, O[nd][1] * invA);
        *(float2*)(oar1 + nd * 8 + 2 * t) = make_float2(O[nd][2] * invB, O[nd][3] * invB);
    }
}

extern "C" void kernel_launch(void* const* d_in, const int* in_sizes, int n_in,
                              void* d_out, int out_size) {
    const float* q = (const float*)d_in[0];
    const float* k = (const float*)d_in[1];
    const float* v = (const float*)d_in[2];
    float* out_attn  = (float*)d_out;
    float* out_probs = (float*)d_out + (size_t)Bn * Tn * Hn * Dn;

    cudaFuncSetAttribute(attn_hmma_kernel,
                         cudaFuncAttributeMaxDynamicSharedMemorySize, SMEM_TOTAL);
    dim3 grid(Tn / MQ, Hn, Bn);   // 16 x 16 x 4 = 1024 CTAs
    attn_hmma_kernel<<<grid, 128, SMEM_TOTAL>>>(q, k, v, out_attn, out_probs);
}

// round 5
// speedup vs baseline: 2.7955x; 1.5761x over previous
#include <cuda_runtime.h>
#include <cuda_bf16.h>
#include <cstdint>

#define Bn 4
#define Tn 1024
#define Sn 1024
#define Hn 16
#define Dn 64
#define RS (Hn*Dn)
#define MQ 64
#define NKC 128
#define NCH (Sn/NKC)

#define TILE_B 16384
#define GRP_B (4*TILE_B)     // per (b,h,chunk): KH,KL,VH,VL tiles

// pre-converted, pre-swizzled bf16 K/V tiles (33.5 MB)
__device__ __align__(128) unsigned char g_kv[(size_t)Bn*Hn*NCH*GRP_B];

// smem regions (main kernel): RK = KH,KL ; RV = VH,VL
#define SM_KH 0
#define SM_KL 16384
#define SM_VH 32768
#define SM_VL 49152
#define SMEM_MAIN 65536

// ---------------- PTX wrappers ----------------
__device__ __forceinline__ uint32_t smem_u32(const void* p) {
    uint32_t a;
    asm("{ .reg .u64 t; cvta.to.shared.u64 t, %1; cvt.u32.u64 %0, t; }" : "=r"(a) : "l"(p));
    return a;
}
__device__ __forceinline__ void ldsm_x4(uint32_t* r, uint32_t addr) {
    asm volatile("ldmatrix.sync.aligned.m8n8.x4.shared.b16 {%0,%1,%2,%3}, [%4];"
        : "=r"(r[0]), "=r"(r[1]), "=r"(r[2]), "=r"(r[3]) : "r"(addr));
}
__device__ __forceinline__ void ldsm_x4_t(uint32_t* r, uint32_t addr) {
    asm volatile("ldmatrix.sync.aligned.m8n8.x4.trans.shared.b16 {%0,%1,%2,%3}, [%4];"
        : "=r"(r[0]), "=r"(r[1]), "=r"(r[2]), "=r"(r[3]) : "r"(addr));
}
__device__ __forceinline__ void mma_bf16(float* c, const uint32_t* a, uint32_t b0, uint32_t b1) {
    asm volatile("mma.sync.aligned.m16n8k16.row.col.f32.bf16.bf16.f32 "
        "{%0,%1,%2,%3}, {%4,%5,%6,%7}, {%8,%9}, {%0,%1,%2,%3};"
        : "+f"(c[0]), "+f"(c[1]), "+f"(c[2]), "+f"(c[3])
        : "r"(a[0]), "r"(a[1]), "r"(a[2]), "r"(a[3]), "r"(b0), "r"(b1));
}
__device__ __forceinline__ void cpa16(uint32_t s, const void* g) {
    asm volatile("cp.async.cg.shared.global [%0], [%1], 16;" :: "r"(s), "l"(g));
}
#define CP_COMMIT() asm volatile("cp.async.commit_group;" ::: "memory")
template<int N> __device__ __forceinline__ void cp_wait() {
    asm volatile("cp.async.wait_group %0;" :: "n"(N) : "memory");
}

__device__ __forceinline__ void split2(float a, float b, uint32_t& hi, uint32_t& lo) {
    __nv_bfloat16 ah = __float2bfloat16(a), bh = __float2bfloat16(b);
    float ar = a - __bfloat162float(ah), br = b - __bfloat162float(bh);
    __nv_bfloat16 al = __float2bfloat16(ar), bl = __float2bfloat16(br);
    hi = ((uint32_t)__bfloat16_as_ushort(bh) << 16) | __bfloat16_as_ushort(ah);
    lo = ((uint32_t)__bfloat16_as_ushort(bl) << 16) | __bfloat16_as_ushort(al);
}

// =================== prep: fp32 K/V -> bf16 hi/lo swizzled tiles ===================
__global__ __launch_bounds__(128)
void prep_kernel(const float* __restrict__ k, const float* __restrict__ v) {
    const int c = blockIdx.x, h = blockIdx.y, b = blockIdx.z, tid = threadIdx.x;
    const float* kb = k + (((size_t)b * Sn + c * NKC) * Hn + h) * Dn;
    const float* vb = v + (((size_t)b * Sn + c * NKC) * Hn + h) * Dn;
    unsigned char* dst = g_kv + (size_t)((b * Hn + h) * NCH + c) * GRP_B;
    #pragma unroll
    for (int u = 0; u < 16; u++) {
        int fid = tid + u * 128;
        int r = fid >> 4, c4 = fid & 15;
        uint32_t off = (uint32_t)(r * 128 + c4 * 8);
        uint32_t so = off ^ ((uint32_t)(r & 7) << 4);
        uint32_t h0, l0, h1, l1;
        float4 x = *(const float4*)(kb + (size_t)r * RS + c4 * 4);
        split2(x.x, x.y, h0, l0); split2(x.z, x.w, h1, l1);
        *(uint2*)(dst + 0 * TILE_B + so) = make_uint2(h0, h1);
        *(uint2*)(dst + 1 * TILE_B + so) = make_uint2(l0, l1);
        float4 y = *(const float4*)(vb + (size_t)r * RS + c4 * 4);
        split2(y.x, y.y, h0, l0); split2(y.z, y.w, h1, l1);
        *(uint2*)(dst + 2 * TILE_B + so) = make_uint2(h0, h1);
        *(uint2*)(dst + 3 * TILE_B + so) = make_uint2(l0, l1);
    }
}

// =================== main attention kernel ===================
__global__ __launch_bounds__(128, 3)
void attn_main(const float* __restrict__ q,
               float* __restrict__ out_attn, float* __restrict__ out_probs) {
    extern __shared__ char sm[];
    const uint32_t smb = smem_u32(sm);
    const int tid = threadIdx.x, lane = tid & 31, w = tid >> 5;
    const int t0 = blockIdx.x * MQ, h = blockIdx.y, b = blockIdx.z;
    const int g = lane >> 2, t = lane & 3;
    const int row0 = t0 + w * 16;

    const unsigned char* kvb = g_kv + (size_t)((b * Hn + h) * NCH) * GRP_B;

    // ---- Q fragments (hi/lo, scale 1/8 folded into Q) ----
    uint32_t qh[4][4], ql[4][4];
    {
        const float* qr0 = q + (((size_t)b * Tn + row0 + g) * Hn + h) * Dn;
        const float* qr1 = qr0 + 8 * RS;
        #pragma unroll
        for (int ks = 0; ks < 4; ks++) {
            float2 f0 = *(const float2*)(qr0 + ks * 16 + 2 * t);
            float2 f1 = *(const float2*)(qr1 + ks * 16 + 2 * t);
            float2 f2 = *(const float2*)(qr0 + ks * 16 + 2 * t + 8);
            float2 f3 = *(const float2*)(qr1 + ks * 16 + 2 * t + 8);
            split2(f0.x * 0.125f, f0.y * 0.125f, qh[ks][0], ql[ks][0]);
            split2(f1.x * 0.125f, f1.y * 0.125f, qh[ks][1], ql[ks][1]);
            split2(f2.x * 0.125f, f2.y * 0.125f, qh[ks][2], ql[ks][2]);
            split2(f3.x * 0.125f, f3.y * 0.125f, qh[ks][3], ql[ks][3]);
        }
    }

    // ldmatrix lane addressing (within-tile SW128)
    const uint32_t rowoff = ((lane >> 4) & 1) * 8 + (lane & 7);
    const uint32_t colsel = ((lane >> 3) & 1) * 16;
    const uint32_t lbase = rowoff * 128 + colsel;
    const uint32_t lxor = (rowoff & 7) << 4;

    float sumA = 0.f, sumB = 0.f;

    // ================= Pass A: rowsums, 1-term QK, double-buffered KH =================
    {
        #pragma unroll
        for (int u = 0; u < 8; u++)
            cpa16(smb + tid * 16 + u * 2048, kvb + 0 * GRP_B + tid * 16 + u * 2048);
        CP_COMMIT();
        #pragma unroll
        for (int u = 0; u < 8; u++)
            cpa16(smb + TILE_B + tid * 16 + u * 2048, kvb + 1 * GRP_B + tid * 16 + u * 2048);
        CP_COMMIT();

        for (int c = 0; c < NCH; c++) {
            cp_wait<1>();
            __syncthreads();
            const uint32_t kb_s = smb + (uint32_t)(c & 1) * TILE_B;

            float S[16][4];
            #pragma unroll
            for (int i = 0; i < 16; i++) { S[i][0] = 0.f; S[i][1] = 0.f; S[i][2] = 0.f; S[i][3] = 0.f; }
            #pragma unroll
            for (int ks = 0; ks < 4; ks++) {
                #pragma unroll
                for (int j = 0; j < 8; j++) {
                    uint32_t bh[4];
                    ldsm_x4(bh, (kb_s + j * 2048 + ks * 32 + lbase) ^ lxor);
                    mma_bf16(S[2 * j],     qh[ks], bh[0], bh[1]);
                    mma_bf16(S[2 * j + 1], qh[ks], bh[2], bh[3]);
                }
            }
            #pragma unroll
            for (int i = 0; i < 16; i++) {
                sumA += __expf(S[i][0]) + __expf(S[i][1]);
                sumB += __expf(S[i][2]) + __expf(S[i][3]);
            }
            __syncthreads();
            if (c + 2 < NCH) {
                const unsigned char* src = kvb + (size_t)(c + 2) * GRP_B;
                uint32_t d = smb + (uint32_t)(c & 1) * TILE_B;
                #pragma unroll
                for (int u = 0; u < 8; u++)
                    cpa16(d + tid * 16 + u * 2048, src + tid * 16 + u * 2048);
            }
            CP_COMMIT();
        }
        cp_wait<0>();
        __syncthreads();
    }
    sumA += __shfl_xor_sync(0xffffffffu, sumA, 1);
    sumA += __shfl_xor_sync(0xffffffffu, sumA, 2);
    sumB += __shfl_xor_sync(0xffffffffu, sumB, 1);
    sumB += __shfl_xor_sync(0xffffffffu, sumB, 2);
    const float invA = 1.f / sumA, invB = 1.f / sumB;

    // ================= Pass B: probs + PV, pipelined K/V =================
    float O[8][4];
    #pragma unroll
    for (int i = 0; i < 8; i++) { O[i][0] = 0.f; O[i][1] = 0.f; O[i][2] = 0.f; O[i][3] = 0.f; }

    // prologue: K0 -> RK, V0 -> RV
    #pragma unroll
    for (int u = 0; u < 16; u++)
        cpa16(smb + SM_KH + tid * 16 + u * 2048, kvb + tid * 16 + u * 2048);
    CP_COMMIT();
    #pragma unroll
    for (int u = 0; u < 16; u++)
        cpa16(smb + SM_VH + tid * 16 + u * 2048, kvb + 32768 + tid * 16 + u * 2048);
    CP_COMMIT();

    float* prowA = out_probs + (((size_t)b * Tn + row0 + g) * Hn + h) * Sn;
    float* prowB = prowA + (size_t)8 * Hn * Sn;

    for (int c = 0; c < NCH; c++) {
        cp_wait<1>();          // K_c resident (V_c still pending)
        __syncthreads();

        float S[16][4];
        #pragma unroll
        for (int i = 0; i < 16; i++) { S[i][0] = 0.f; S[i][1] = 0.f; S[i][2] = 0.f; S[i][3] = 0.f; }
        #pragma unroll
        for (int ks = 0; ks < 4; ks++) {
            #pragma unroll
            for (int j = 0; j < 8; j++) {
                uint32_t bh[4], bl[4];
                ldsm_x4(bh, (smb + SM_KH + j * 2048 + ks * 32 + lbase) ^ lxor);
                ldsm_x4(bl, (smb + SM_KL + j * 2048 + ks * 32 + lbase) ^ lxor);
                mma_bf16(S[2 * j],     qh[ks], bh[0], bh[1]);
                mma_bf16(S[2 * j],     qh[ks], bl[0], bl[1]);
                mma_bf16(S[2 * j],     ql[ks], bh[0], bh[1]);
                mma_bf16(S[2 * j + 1], qh[ks], bh[2], bh[3]);
                mma_bf16(S[2 * j + 1], qh[ks], bl[2], bl[3]);
                mma_bf16(S[2 * j + 1], ql[ks], bh[2], bh[3]);
            }
        }
        __syncthreads();       // all warps done reading RK
        {                      // prefetch K_{c+1}
            const unsigned char* src = kvb + (size_t)((c + 1) & (NCH - 1)) * GRP_B;
            #pragma unroll
            for (int u = 0; u < 16; u++)
                cpa16(smb + SM_KH + tid * 16 + u * 2048, src + tid * 16 + u * 2048);
            CP_COMMIT();
        }
        cp_wait<1>();          // V_c resident (K_{c+1} pending)
        __syncthreads();

        // fused exp / probs store / split / PV
        #pragma unroll
        for (int ks = 0; ks < 8; ks++) {
            float e0 = __expf(S[2 * ks][0]),     e1 = __expf(S[2 * ks][1]);
            float e2 = __expf(S[2 * ks][2]),     e3 = __expf(S[2 * ks][3]);
            float e4 = __expf(S[2 * ks + 1][0]), e5 = __expf(S[2 * ks + 1][1]);
            float e6 = __expf(S[2 * ks + 1][2]), e7 = __expf(S[2 * ks + 1][3]);

            *(float2*)(prowA + c * 128 + 16 * ks + 2 * t)     = make_float2(e0 * invA, e1 * invA);
            *(float2*)(prowA + c * 128 + 16 * ks + 8 + 2 * t) = make_float2(e4 * invA, e5 * invA);
            *(float2*)(prowB + c * 128 + 16 * ks + 2 * t)     = make_float2(e2 * invB, e3 * invB);
            *(float2*)(prowB + c * 128 + 16 * ks + 8 + 2 * t) = make_float2(e6 * invB, e7 * invB);

            uint32_t ah[4], al[4];
            split2(e0, e1, ah[0], al[0]); split2(e2, e3, ah[1], al[1]);
            split2(e4, e5, ah[2], al[2]); split2(e6, e7, ah[3], al[3]);

            #pragma unroll
            for (int p = 0; p < 4; p++) {
                uint32_t bh[4], bl[4];
                ldsm_x4_t(bh, (smb + SM_VH + ks * 2048 + p * 32 + lbase) ^ lxor);
                ldsm_x4_t(bl, (smb + SM_VL + ks * 2048 + p * 32 + lbase) ^ lxor);
                mma_bf16(O[2 * p],     ah, bh[0], bh[2]);
                mma_bf16(O[2 * p],     ah, bl[0], bl[2]);
                mma_bf16(O[2 * p],     al, bh[0], bh[2]);
                mma_bf16(O[2 * p + 1], ah, bh[1], bh[3]);
                mma_bf16(O[2 * p + 1], ah, bl[1], bl[3]);
                mma_bf16(O[2 * p + 1], al, bh[1], bh[3]);
            }
        }
        __syncthreads();       // all warps done reading RV
        {                      // prefetch V_{c+1}
            const unsigned char* src = kvb + (size_t)((c + 1) & (NCH - 1)) * GRP_B + 32768;
            #pragma unroll
            for (int u = 0; u < 16; u++)
                cpa16(smb + SM_VH + tid * 16 + u * 2048, src + tid * 16 + u * 2048);
            CP_COMMIT();
        }
    }

    // ================= attn output =================
    float* oar0 = out_attn + (((size_t)b * Tn + row0 + g) * Hn + h) * Dn;
    float* oar1 = oar0 + 8 * RS;
    #pragma unroll
    for (int nd = 0; nd < 8; nd++) {
        *(float2*)(oar0 + nd * 8 + 2 * t) = make_float2(O[nd][0] * invA, O[nd][1] * invA);
        *(float2*)(oar1 + nd * 8 + 2 * t) = make_float2(O[nd][2] * invB, O[nd][3] * invB);
    }
}

extern "C" void kernel_launch(void* const* d_in, const int* in_sizes, int n_in,
                              void* d_out, int out_size) {
    const float* q = (const float*)d_in[0];
    const float* k = (const float*)d_in[1];
    const float* v = (const float*)d_in[2];
    float* out_attn  = (float*)d_out;
    float* out_probs = (float*)d_out + (size_t)Bn * Tn * Hn * Dn;

    cudaFuncSetAttribute(attn_main,
                         cudaFuncAttributeMaxDynamicSharedMemorySize, SMEM_MAIN);

    dim3 pgrid(NCH, Hn, Bn);
    prep_kernel<<<pgrid, 128>>>(k, v);

    dim3 grid(Tn / MQ, Hn, Bn);
    attn_main<<<grid, 128, SMEM_MAIN>>>(q, out_attn, out_probs);
}

// round 6
// speedup vs baseline: 3.2535x; 1.1638x over previous
#include <cuda_runtime.h>
#include <cuda_bf16.h>
#include <cstdint>

#define Bn 4
#define Tn 1024
#define Sn 1024
#define Hn 16
#define Dn 64
#define RS (Hn*Dn)
#define MQ 64
#define NKC 128
#define NCH (Sn/NKC)
#define NT 256

#define TILE_B 16384
#define GRP_B (4*TILE_B)     // per (b,h,chunk): KH,KL,VH,VL

__device__ __align__(128) unsigned char g_kv[(size_t)Bn*Hn*NCH*GRP_B];

#define SM_KH 0
#define SM_KL 16384
#define SM_VH 32768
#define SM_VL 49152
#define SM_SUMS 65536
#define SMEM_MAIN 66048

// ---------------- PTX wrappers ----------------
__device__ __forceinline__ uint32_t smem_u32(const void* p) {
    uint32_t a;
    asm("{ .reg .u64 t; cvta.to.shared.u64 t, %1; cvt.u32.u64 %0, t; }" : "=r"(a) : "l"(p));
    return a;
}
__device__ __forceinline__ void ldsm_x4(uint32_t* r, uint32_t addr) {
    asm volatile("ldmatrix.sync.aligned.m8n8.x4.shared.b16 {%0,%1,%2,%3}, [%4];"
        : "=r"(r[0]), "=r"(r[1]), "=r"(r[2]), "=r"(r[3]) : "r"(addr));
}
__device__ __forceinline__ void ldsm_x4_t(uint32_t* r, uint32_t addr) {
    asm volatile("ldmatrix.sync.aligned.m8n8.x4.trans.shared.b16 {%0,%1,%2,%3}, [%4];"
        : "=r"(r[0]), "=r"(r[1]), "=r"(r[2]), "=r"(r[3]) : "r"(addr));
}
__device__ __forceinline__ void mma_bf16(float* c, const uint32_t* a, uint32_t b0, uint32_t b1) {
    asm volatile("mma.sync.aligned.m16n8k16.row.col.f32.bf16.bf16.f32 "
        "{%0,%1,%2,%3}, {%4,%5,%6,%7}, {%8,%9}, {%0,%1,%2,%3};"
        : "+f"(c[0]), "+f"(c[1]), "+f"(c[2]), "+f"(c[3])
        : "r"(a[0]), "r"(a[1]), "r"(a[2]), "r"(a[3]), "r"(b0), "r"(b1));
}
__device__ __forceinline__ void cpa16(uint32_t s, const void* g) {
    asm volatile("cp.async.cg.shared.global [%0], [%1], 16;" :: "r"(s), "l"(g));
}
#define CP_COMMIT() asm volatile("cp.async.commit_group;" ::: "memory")
template<int N> __device__ __forceinline__ void cp_wait() {
    asm volatile("cp.async.wait_group %0;" :: "n"(N) : "memory");
}

__device__ __forceinline__ void split2(float a, float b, uint32_t& hi, uint32_t& lo) {
    __nv_bfloat16 ah = __float2bfloat16(a), bh = __float2bfloat16(b);
    float ar = a - __bfloat162float(ah), br = b - __bfloat162float(bh);
    __nv_bfloat16 al = __float2bfloat16(ar), bl = __float2bfloat16(br);
    hi = ((uint32_t)__bfloat16_as_ushort(bh) << 16) | __bfloat16_as_ushort(ah);
    lo = ((uint32_t)__bfloat16_as_ushort(bl) << 16) | __bfloat16_as_ushort(al);
}

// =================== prep: fp32 K/V -> bf16 hi/lo swizzled tiles ===================
__global__ __launch_bounds__(128)
void prep_kernel(const float* __restrict__ k, const float* __restrict__ v) {
    const int c = blockIdx.x, h = blockIdx.y, b = blockIdx.z, tid = threadIdx.x;
    const float* kb = k + (((size_t)b * Sn + c * NKC) * Hn + h) * Dn;
    const float* vb = v + (((size_t)b * Sn + c * NKC) * Hn + h) * Dn;
    unsigned char* dst = g_kv + (size_t)((b * Hn + h) * NCH + c) * GRP_B;
    #pragma unroll
    for (int u = 0; u < 16; u++) {
        int fid = tid + u * 128;
        int r = fid >> 4, c4 = fid & 15;
        uint32_t off = (uint32_t)(r * 128 + c4 * 8);
        uint32_t so = off ^ ((uint32_t)(r & 7) << 4);
        uint32_t h0, l0, h1, l1;
        float4 x = *(const float4*)(kb + (size_t)r * RS + c4 * 4);
        split2(x.x, x.y, h0, l0); split2(x.z, x.w, h1, l1);
        *(uint2*)(dst + 0 * TILE_B + so) = make_uint2(h0, h1);
        *(uint2*)(dst + 1 * TILE_B + so) = make_uint2(l0, l1);
        float4 y = *(const float4*)(vb + (size_t)r * RS + c4 * 4);
        split2(y.x, y.y, h0, l0); split2(y.z, y.w, h1, l1);
        *(uint2*)(dst + 2 * TILE_B + so) = make_uint2(h0, h1);
        *(uint2*)(dst + 3 * TILE_B + so) = make_uint2(l0, l1);
    }
}

// =================== main attention kernel ===================
__global__ __launch_bounds__(NT, 2)
void attn_main(const float* __restrict__ q,
               float* __restrict__ out_attn, float* __restrict__ out_probs) {
    extern __shared__ char sm[];
    const uint32_t smb = smem_u32(sm);
    const int tid = threadIdx.x, lane = tid & 31, w = tid >> 5;
    const int wp = w & 3, half = w >> 2;          // warp pair id / key half
    const int t0 = blockIdx.x * MQ, h = blockIdx.y, b = blockIdx.z;
    const int g = lane >> 2, t = lane & 3;
    const int row0 = t0 + wp * 16;

    const unsigned char* kvb = g_kv + (size_t)((b * Hn + h) * NCH) * GRP_B;

    // ---- Q fragments (hi/lo, scale 1/8 folded into Q) ----
    uint32_t qh[4][4], ql[4][4];
    {
        const float* qr0 = q + (((size_t)b * Tn + row0 + g) * Hn + h) * Dn;
        const float* qr1 = qr0 + 8 * RS;
        #pragma unroll
        for (int ks = 0; ks < 4; ks++) {
            float2 f0 = *(const float2*)(qr0 + ks * 16 + 2 * t);
            float2 f1 = *(const float2*)(qr1 + ks * 16 + 2 * t);
            float2 f2 = *(const float2*)(qr0 + ks * 16 + 2 * t + 8);
            float2 f3 = *(const float2*)(qr1 + ks * 16 + 2 * t + 8);
            split2(f0.x * 0.125f, f0.y * 0.125f, qh[ks][0], ql[ks][0]);
            split2(f1.x * 0.125f, f1.y * 0.125f, qh[ks][1], ql[ks][1]);
            split2(f2.x * 0.125f, f2.y * 0.125f, qh[ks][2], ql[ks][2]);
            split2(f3.x * 0.125f, f3.y * 0.125f, qh[ks][3], ql[ks][3]);
        }
    }

    // ldmatrix lane addressing (within-tile SW128)
    const uint32_t rowoff = ((lane >> 4) & 1) * 8 + (lane & 7);
    const uint32_t colsel = ((lane >> 3) & 1) * 16;
    const uint32_t lbase = rowoff * 128 + colsel;
    const uint32_t lxor = (rowoff & 7) << 4;

    float sumA = 0.f, sumB = 0.f;

    // ================= Pass A: rowsums (1-term, KH only, double-buffered) =================
    {
        #pragma unroll
        for (int u = 0; u < 4; u++)
            cpa16(smb + tid * 16 + u * 4096, kvb + tid * 16 + u * 4096);
        CP_COMMIT();
        #pragma unroll
        for (int u = 0; u < 4; u++)
            cpa16(smb + TILE_B + tid * 16 + u * 4096, kvb + GRP_B + tid * 16 + u * 4096);
        CP_COMMIT();

        for (int c = 0; c < NCH; c++) {
            cp_wait<1>();
            __syncthreads();
            const uint32_t kb_s = smb + (uint32_t)(c & 1) * TILE_B;

            float S[8][4];
            #pragma unroll
            for (int i = 0; i < 8; i++) { S[i][0] = 0.f; S[i][1] = 0.f; S[i][2] = 0.f; S[i][3] = 0.f; }
            #pragma unroll
            for (int ks = 0; ks < 4; ks++) {
                #pragma unroll
                for (int j = 0; j < 4; j++) {
                    const int jj = half * 4 + j;
                    uint32_t bh[4];
                    ldsm_x4(bh, (kb_s + jj * 2048 + ks * 32 + lbase) ^ lxor);
                    mma_bf16(S[2 * j],     qh[ks], bh[0], bh[1]);
                    mma_bf16(S[2 * j + 1], qh[ks], bh[2], bh[3]);
                }
            }
            #pragma unroll
            for (int i = 0; i < 8; i++) {
                sumA += __expf(S[i][0]) + __expf(S[i][1]);
                sumB += __expf(S[i][2]) + __expf(S[i][3]);
            }
            __syncthreads();
            if (c + 2 < NCH) {
                const unsigned char* src = kvb + (size_t)(c + 2) * GRP_B;
                uint32_t d = smb + (uint32_t)(c & 1) * TILE_B;
                #pragma unroll
                for (int u = 0; u < 4; u++)
                    cpa16(d + tid * 16 + u * 4096, src + tid * 16 + u * 4096);
            }
            CP_COMMIT();
        }
        cp_wait<0>();
        __syncthreads();
    }
    sumA += __shfl_xor_sync(0xffffffffu, sumA, 1);
    sumA += __shfl_xor_sync(0xffffffffu, sumA, 2);
    sumB += __shfl_xor_sync(0xffffffffu, sumB, 1);
    sumB += __shfl_xor_sync(0xffffffffu, sumB, 2);

    // pass B prologue copies (overlap with sum exchange)
    #pragma unroll
    for (int u = 0; u < 8; u++)
        cpa16(smb + SM_KH + tid * 16 + u * 4096, kvb + tid * 16 + u * 4096);
    CP_COMMIT();
    #pragma unroll
    for (int u = 0; u < 8; u++)
        cpa16(smb + SM_VH + tid * 16 + u * 4096, kvb + 32768 + tid * 16 + u * 4096);
    CP_COMMIT();

    // cross-half rowsum exchange
    {
        float* ss = (float*)(sm + SM_SUMS);
        if (t == 0) { ss[w * 16 + g * 2] = sumA; ss[w * 16 + g * 2 + 1] = sumB; }
        __syncthreads();
        sumA += ss[(w ^ 4) * 16 + g * 2];
        sumB += ss[(w ^ 4) * 16 + g * 2 + 1];
    }
    const float invA = 1.f / sumA, invB = 1.f / sumB;

    // ================= Pass B: probs + PV =================
    float O[8][4];
    #pragma unroll
    for (int i = 0; i < 8; i++) { O[i][0] = 0.f; O[i][1] = 0.f; O[i][2] = 0.f; O[i][3] = 0.f; }

    float* prowA = out_probs + (((size_t)b * Tn + row0 + g) * Hn + h) * Sn;
    float* prowB = prowA + (size_t)8 * Hn * Sn;

    for (int c = 0; c < NCH; c++) {
        cp_wait<1>();          // K_c resident
        __syncthreads();

        float S[8][4];
        #pragma unroll
        for (int i = 0; i < 8; i++) { S[i][0] = 0.f; S[i][1] = 0.f; S[i][2] = 0.f; S[i][3] = 0.f; }
        #pragma unroll
        for (int ks = 0; ks < 4; ks++) {
            #pragma unroll
            for (int j = 0; j < 4; j++) {
                const int jj = half * 4 + j;
                uint32_t bh[4], bl[4];
                ldsm_x4(bh, (smb + SM_KH + jj * 2048 + ks * 32 + lbase) ^ lxor);
                ldsm_x4(bl, (smb + SM_KL + jj * 2048 + ks * 32 + lbase) ^ lxor);
                mma_bf16(S[2 * j],     qh[ks], bh[0], bh[1]);
                mma_bf16(S[2 * j],     qh[ks], bl[0], bl[1]);
                mma_bf16(S[2 * j],     ql[ks], bh[0], bh[1]);
                mma_bf16(S[2 * j + 1], qh[ks], bh[2], bh[3]);
                mma_bf16(S[2 * j + 1], qh[ks], bl[2], bl[3]);
                mma_bf16(S[2 * j + 1], ql[ks], bh[2], bh[3]);
            }
        }
        __syncthreads();       // done reading K region
        if (c + 1 < NCH) {
            const unsigned char* src = kvb + (size_t)(c + 1) * GRP_B;
            #pragma unroll
            for (int u = 0; u < 8; u++)
                cpa16(smb + SM_KH + tid * 16 + u * 4096, src + tid * 16 + u * 4096);
        }
        CP_COMMIT();
        cp_wait<1>();          // V_c resident
        __syncthreads();

        // fused exp / probs store / split / PV (this warp's 64-key half)
        #pragma unroll
        for (int ks = 0; ks < 4; ks++) {
            const int kk = half * 4 + ks;
            float e0 = __expf(S[2 * ks][0]),     e1 = __expf(S[2 * ks][1]);
            float e2 = __expf(S[2 * ks][2]),     e3 = __expf(S[2 * ks][3]);
            float e4 = __expf(S[2 * ks + 1][0]), e5 = __expf(S[2 * ks + 1][1]);
            float e6 = __expf(S[2 * ks + 1][2]), e7 = __expf(S[2 * ks + 1][3]);

            *(float2*)(prowA + c * 128 + kk * 16 + 2 * t)     = make_float2(e0 * invA, e1 * invA);
            *(float2*)(prowA + c * 128 + kk * 16 + 8 + 2 * t) = make_float2(e4 * invA, e5 * invA);
            *(float2*)(prowB + c * 128 + kk * 16 + 2 * t)     = make_float2(e2 * invB, e3 * invB);
            *(float2*)(prowB + c * 128 + kk * 16 + 8 + 2 * t) = make_float2(e6 * invB, e7 * invB);

            uint32_t ah[4], al[4];
            split2(e0, e1, ah[0], al[0]); split2(e2, e3, ah[1], al[1]);
            split2(e4, e5, ah[2], al[2]); split2(e6, e7, ah[3], al[3]);

            #pragma unroll
            for (int p = 0; p < 4; p++) {
                uint32_t bh[4], bl[4];
                ldsm_x4_t(bh, (smb + SM_VH + kk * 2048 + p * 32 + lbase) ^ lxor);
                ldsm_x4_t(bl, (smb + SM_VL + kk * 2048 + p * 32 + lbase) ^ lxor);
                mma_bf16(O[2 * p],     ah, bh[0], bh[2]);
                mma_bf16(O[2 * p],     ah, bl[0], bl[2]);
                mma_bf16(O[2 * p],     al, bh[0], bh[2]);
                mma_bf16(O[2 * p + 1], ah, bh[1], bh[3]);
                mma_bf16(O[2 * p + 1], ah, bl[1], bl[3]);
                mma_bf16(O[2 * p + 1], al, bh[1], bh[3]);
            }
        }
        __syncthreads();       // done reading V region
        if (c + 1 < NCH) {
            const unsigned char* src = kvb + (size_t)(c + 1) * GRP_B + 32768;
            #pragma unroll
            for (int u = 0; u < 8; u++)
                cpa16(smb + SM_VH + tid * 16 + u * 4096, src + tid * 16 + u * 4096);
        }
        CP_COMMIT();
    }
    cp_wait<0>();
    __syncthreads();

    // ================= cross-half O reduction + output =================
    {
        float* red = (float*)(sm + SM_KH) + wp * 1024;    // 16x64 region per pair
        if (half == 1) {
            #pragma unroll
            for (int nd = 0; nd < 8; nd++) {
                red[ g      * 64 + nd * 8 + 2 * t]     = O[nd][0];
                red[ g      * 64 + nd * 8 + 2 * t + 1] = O[nd][1];
                red[(g + 8) * 64 + nd * 8 + 2 * t]     = O[nd][2];
                red[(g + 8) * 64 + nd * 8 + 2 * t + 1] = O[nd][3];
            }
        }
        __syncthreads();
        if (half == 0) {
            float* oar0 = out_attn + (((size_t)b * Tn + row0 + g) * Hn + h) * Dn;
            float* oar1 = oar0 + 8 * RS;
            #pragma unroll
            for (int nd = 0; nd < 8; nd++) {
                float o0 = O[nd][0] + red[ g      * 64 + nd * 8 + 2 * t];
                float o1 = O[nd][1] + red[ g      * 64 + nd * 8 + 2 * t + 1];
                float o2 = O[nd][2] + red[(g + 8) * 64 + nd * 8 + 2 * t];
                float o3 = O[nd][3] + red[(g + 8) * 64 + nd * 8 + 2 * t + 1];
                *(float2*)(oar0 + nd * 8 + 2 * t) = make_float2(o0 * invA, o1 * invA);
                *(float2*)(oar1 + nd * 8 + 2 * t) = make_float2(o2 * invB, o3 * invB);
            }
        }
    }
}

extern "C" void kernel_launch(void* const* d_in, const int* in_sizes, int n_in,
                              void* d_out, int out_size) {
    const float* q = (const float*)d_in[0];
    const float* k = (const float*)d_in[1];
    const float* v = (const float*)d_in[2];
    float* out_attn  = (float*)d_out;
    float* out_probs = (float*)d_out + (size_t)Bn * Tn * Hn * Dn;

    cudaFuncSetAttribute(attn_main,
                         cudaFuncAttributeMaxDynamicSharedMemorySize, SMEM_MAIN);

    dim3 pgrid(NCH, Hn, Bn);
    prep_kernel<<<pgrid, 128>>>(k, v);

    dim3 grid(Tn / MQ, Hn, Bn);
    attn_main<<<grid, NT, SMEM_MAIN>>>(q, out_attn, out_probs);
}

// round 7
// speedup vs baseline: 3.8828x; 1.1934x over previous
#include <cuda_runtime.h>
#include <cuda_fp16.h>
#include <cstdint>

#define Bn 4
#define Tn 1024
#define Sn 1024
#define Hn 16
#define Dn 64
#define RS (Hn*Dn)
#define MQ 64
#define NKC 128
#define NCH (Sn/NKC)
#define NT 256

// per-(b,h,chunk) scratch group: [K fp16 16KB][K tf32 32KB][V tf32 32KB]
#define CH_B 81920
#define OFF_KF 0
#define OFF_KT 16384
#define OFF_VT 49152
__device__ __align__(128) unsigned char g_kv[(size_t)Bn*Hn*NCH*CH_B];   // 40 MB

// main-kernel smem
#define SM_K 0
#define SM_V 32768
#define SM_SUMS 65536
#define SMEM_MAIN 66048

// ---------------- PTX wrappers ----------------
__device__ __forceinline__ uint32_t smem_u32(const void* p) {
    uint32_t a;
    asm("{ .reg .u64 t; cvta.to.shared.u64 t, %1; cvt.u32.u64 %0, t; }" : "=r"(a) : "l"(p));
    return a;
}
__device__ __forceinline__ void ldsm_x4(uint32_t* r, uint32_t addr) {
    asm volatile("ldmatrix.sync.aligned.m8n8.x4.shared.b16 {%0,%1,%2,%3}, [%4];"
        : "=r"(r[0]), "=r"(r[1]), "=r"(r[2]), "=r"(r[3]) : "r"(addr));
}
__device__ __forceinline__ void mma_f16(float* c, const uint32_t* a, uint32_t b0, uint32_t b1) {
    asm volatile("mma.sync.aligned.m16n8k16.row.col.f32.f16.f16.f32 "
        "{%0,%1,%2,%3}, {%4,%5,%6,%7}, {%8,%9}, {%0,%1,%2,%3};"
        : "+f"(c[0]), "+f"(c[1]), "+f"(c[2]), "+f"(c[3])
        : "r"(a[0]), "r"(a[1]), "r"(a[2]), "r"(a[3]), "r"(b0), "r"(b1));
}
__device__ __forceinline__ void mma_tf32(float* c, const uint32_t* a, uint32_t b0, uint32_t b1) {
    asm volatile("mma.sync.aligned.m16n8k8.row.col.f32.tf32.tf32.f32 "
        "{%0,%1,%2,%3}, {%4,%5,%6,%7}, {%8,%9}, {%0,%1,%2,%3};"
        : "+f"(c[0]), "+f"(c[1]), "+f"(c[2]), "+f"(c[3])
        : "r"(a[0]), "r"(a[1]), "r"(a[2]), "r"(a[3]), "r"(b0), "r"(b1));
}
__device__ __forceinline__ void cpa16(uint32_t s, const void* g) {
    asm volatile("cp.async.cg.shared.global [%0], [%1], 16;" :: "r"(s), "l"(g));
}
#define CP_COMMIT() asm volatile("cp.async.commit_group;" ::: "memory")
template<int N> __device__ __forceinline__ void cp_wait() {
    asm volatile("cp.async.wait_group %0;" :: "n"(N) : "memory");
}
__device__ __forceinline__ uint32_t f2tf32(float x) {
    uint32_t r;
    asm("cvt.rna.tf32.f32 %0, %1;" : "=r"(r) : "f"(x));
    return r;
}
__device__ __forceinline__ uint32_t packh2(float a, float b) {
    __half2 h = __floats2half2_rn(a, b);
    return *(uint32_t*)&h;
}

// =================== prep: fp32 K/V -> fp16 K tile + tf32 block-layout K/V ===================
__global__ __launch_bounds__(128)
void prep_kernel(const float* __restrict__ k, const float* __restrict__ v) {
    const int c = blockIdx.x, h = blockIdx.y, b = blockIdx.z, tid = threadIdx.x;
    const float* kb = k + (((size_t)b * Sn + c * NKC) * Hn + h) * Dn;
    const float* vb = v + (((size_t)b * Sn + c * NKC) * Hn + h) * Dn;
    unsigned char* dst = g_kv + (size_t)((b * Hn + h) * NCH + c) * CH_B;
    #pragma unroll
    for (int u = 0; u < 16; u++) {
        int fid = tid + u * 128;
        int r = fid >> 4, c4 = fid & 15;        // key r, dims c4*4..c4*4+3
        // ---- K ----
        float4 x = *(const float4*)(kb + (size_t)r * RS + c4 * 4);
        {   // fp16 tile, 128B rows, SW128-style swizzle (pass A)
            uint32_t off = (uint32_t)(r * 128 + c4 * 8);
            uint32_t so = off ^ ((uint32_t)(r & 7) << 4);
            *(uint2*)(dst + OFF_KF + so) = make_uint2(packh2(x.x, x.y), packh2(x.z, x.w));
        }
        {   // tf32 blocks: (bk = dim-step, bn = key-tile)
            int bk = c4 >> 1, khalf = c4 & 1;
            int bn = r >> 3, nn = r & 7;
            uint32_t base = (uint32_t)(((bn >> 1) * 8 + bk) * 512 + (bn & 1) * 256);
            uint32_t woff = (uint32_t)(nn * 32 + ((khalf ^ (nn >> 2)) ? 16 : 0));
            uint4 val = make_uint4(f2tf32(x.x), f2tf32(x.y), f2tf32(x.z), f2tf32(x.w));
            *(uint4*)(dst + OFF_KT + base + woff) = val;
        }
        // ---- V ---- tf32 blocks: (bk = key-step, bn = dim-tile)
        float4 y = *(const float4*)(vb + (size_t)r * RS + c4 * 4);
        {
            int bk = r >> 3, kk = r & 7;
            int bn = c4 >> 1, nhalf = c4 & 1;
            uint32_t base = (uint32_t)(((bn >> 1) * 16 + bk) * 512 + (bn & 1) * 256);
            uint32_t sel = (uint32_t)((((kk >> 2) ^ nhalf) ? 16 : 0) + (kk & 3) * 4);
            float yy[4] = {y.x, y.y, y.z, y.w};
            #pragma unroll
            for (int i = 0; i < 4; i++) {
                uint32_t nn = nhalf * 4 + i;
                *(uint32_t*)(dst + OFF_VT + base + nn * 32 + sel) = f2tf32(yy[i]);
            }
        }
    }
}

// =================== main attention kernel ===================
__global__ __launch_bounds__(NT, 2)
void attn_main(const float* __restrict__ q,
               float* __restrict__ out_attn, float* __restrict__ out_probs) {
    extern __shared__ char sm[];
    const uint32_t smb = smem_u32(sm);
    const int tid = threadIdx.x, lane = tid & 31, w = tid >> 5;
    const int wp = w & 3, half = w >> 2;
    const int t0 = blockIdx.x * MQ, h = blockIdx.y, b = blockIdx.z;
    const int g = lane >> 2, t = lane & 3;
    const int row0 = t0 + wp * 16;

    const unsigned char* kvb = g_kv + (size_t)((b * Hn + h) * NCH) * CH_B;
    const float* qr0 = q + (((size_t)b * Tn + row0 + g) * Hn + h) * Dn;
    const float* qr1 = qr0 + 8 * RS;

    // ---- Q fp16 fragments for pass A (scale 1/8 folded into Q) ----
    uint32_t qf[4][4];
    #pragma unroll
    for (int ks = 0; ks < 4; ks++) {
        float2 f0 = *(const float2*)(qr0 + ks * 16 + 2 * t);
        float2 f1 = *(const float2*)(qr1 + ks * 16 + 2 * t);
        float2 f2 = *(const float2*)(qr0 + ks * 16 + 2 * t + 8);
        float2 f3 = *(const float2*)(qr1 + ks * 16 + 2 * t + 8);
        qf[ks][0] = packh2(f0.x * 0.125f, f0.y * 0.125f);
        qf[ks][1] = packh2(f1.x * 0.125f, f1.y * 0.125f);
        qf[ks][2] = packh2(f2.x * 0.125f, f2.y * 0.125f);
        qf[ks][3] = packh2(f3.x * 0.125f, f3.y * 0.125f);
    }

    // fp16-tile ldmatrix addressing (pass A)
    const uint32_t rowoff = ((lane >> 4) & 1) * 8 + (lane & 7);
    const uint32_t colsel = ((lane >> 3) & 1) * 16;
    const uint32_t lbase = rowoff * 128 + colsel;
    const uint32_t lxor = (rowoff & 7) << 4;

    // tf32 block ldmatrix per-lane offset
    const uint32_t r8 = lane & 7, mhalf = (lane >> 3) & 1, msel = (uint32_t)lane >> 4;
    const uint32_t ldoff = msel * 256 + r8 * 32 + ((((r8 >> 2) & 1) ^ mhalf) ? 16u : 0u);

    float sumA = 0.f, sumB = 0.f;

    // ================= Pass A: rowsums (fp16 1-term, double-buffered 16KB tiles) =================
    {
        #pragma unroll
        for (int u = 0; u < 4; u++)
            cpa16(smb + tid * 16 + u * 4096, kvb + OFF_KF + tid * 16 + u * 4096);
        CP_COMMIT();
        #pragma unroll
        for (int u = 0; u < 4; u++)
            cpa16(smb + 16384 + tid * 16 + u * 4096, kvb + CH_B + OFF_KF + tid * 16 + u * 4096);
        CP_COMMIT();

        for (int c = 0; c < NCH; c++) {
            cp_wait<1>();
            __syncthreads();
            const uint32_t kb_s = smb + (uint32_t)(c & 1) * 16384;

            float S[8][4];
            #pragma unroll
            for (int i = 0; i < 8; i++) { S[i][0] = 0.f; S[i][1] = 0.f; S[i][2] = 0.f; S[i][3] = 0.f; }
            #pragma unroll
            for (int ks = 0; ks < 4; ks++) {
                #pragma unroll
                for (int j = 0; j < 4; j++) {
                    const int jj = half * 4 + j;
                    uint32_t bh[4];
                    ldsm_x4(bh, (kb_s + jj * 2048 + ks * 32 + lbase) ^ lxor);
                    mma_f16(S[2 * j],     qf[ks], bh[0], bh[1]);
                    mma_f16(S[2 * j + 1], qf[ks], bh[2], bh[3]);
                }
            }
            #pragma unroll
            for (int i = 0; i < 8; i++) {
                sumA += __expf(S[i][0]) + __expf(S[i][1]);
                sumB += __expf(S[i][2]) + __expf(S[i][3]);
            }
            __syncthreads();
            if (c + 2 < NCH) {
                const unsigned char* src = kvb + (size_t)(c + 2) * CH_B + OFF_KF;
                uint32_t d = smb + (uint32_t)(c & 1) * 16384;
                #pragma unroll
                for (int u = 0; u < 4; u++)
                    cpa16(d + tid * 16 + u * 4096, src + tid * 16 + u * 4096);
            }
            CP_COMMIT();
        }
        cp_wait<0>();
        __syncthreads();
    }
    sumA += __shfl_xor_sync(0xffffffffu, sumA, 1);
    sumA += __shfl_xor_sync(0xffffffffu, sumA, 2);
    sumB += __shfl_xor_sync(0xffffffffu, sumB, 1);
    sumB += __shfl_xor_sync(0xffffffffu, sumB, 2);

    // ---- Q tf32 fragments for pass B ----
    uint32_t qa[8][4];
    #pragma unroll
    for (int s = 0; s < 8; s++) {
        qa[s][0] = f2tf32(qr0[8 * s + t]     * 0.125f);
        qa[s][1] = f2tf32(qr1[8 * s + t]     * 0.125f);
        qa[s][2] = f2tf32(qr0[8 * s + t + 4] * 0.125f);
        qa[s][3] = f2tf32(qr1[8 * s + t + 4] * 0.125f);
    }

    // pass B prologue: K0, V0
    #pragma unroll
    for (int u = 0; u < 8; u++)
        cpa16(smb + SM_K + tid * 16 + u * 4096, kvb + OFF_KT + tid * 16 + u * 4096);
    CP_COMMIT();
    #pragma unroll
    for (int u = 0; u < 8; u++)
        cpa16(smb + SM_V + tid * 16 + u * 4096, kvb + OFF_VT + tid * 16 + u * 4096);
    CP_COMMIT();

    // cross-half rowsum exchange
    {
        float* ss = (float*)(sm + SM_SUMS);
        if (t == 0) { ss[w * 16 + g * 2] = sumA; ss[w * 16 + g * 2 + 1] = sumB; }
        __syncthreads();
        sumA += ss[(w ^ 4) * 16 + g * 2];
        sumB += ss[(w ^ 4) * 16 + g * 2 + 1];
    }
    const float invA = 1.f / sumA, invB = 1.f / sumB;

    // ================= Pass B: probs + PV (tf32 1-term) =================
    float O[8][4];
    #pragma unroll
    for (int i = 0; i < 8; i++) { O[i][0] = 0.f; O[i][1] = 0.f; O[i][2] = 0.f; O[i][3] = 0.f; }

    float* prowA = out_probs + (((size_t)b * Tn + row0 + g) * Hn + h) * Sn;
    float* prowB = prowA + (size_t)8 * Hn * Sn;
    const int srcl  = (lane & 28) + (t >> 1);
    const int srcl2 = srcl + 2;

    for (int c = 0; c < NCH; c++) {
        cp_wait<1>();          // K_c resident
        __syncthreads();

        float S[8][4];
        #pragma unroll
        for (int i = 0; i < 8; i++) { S[i][0] = 0.f; S[i][1] = 0.f; S[i][2] = 0.f; S[i][3] = 0.f; }
        #pragma unroll
        for (int s = 0; s < 8; s++) {
            #pragma unroll
            for (int p = 0; p < 4; p++) {
                uint32_t bb[4];
                ldsm_x4(bb, smb + SM_K + (uint32_t)(((half * 4 + p) * 8 + s) * 512) + ldoff);
                mma_tf32(S[2 * p],     qa[s], bb[0], bb[1]);
                mma_tf32(S[2 * p + 1], qa[s], bb[2], bb[3]);
            }
        }
        __syncthreads();       // done reading K region
        if (c + 1 < NCH) {
            const unsigned char* src = kvb + (size_t)(c + 1) * CH_B + OFF_KT;
            #pragma unroll
            for (int u = 0; u < 8; u++)
                cpa16(smb + SM_K + tid * 16 + u * 4096, src + tid * 16 + u * 4096);
        }
        CP_COMMIT();
        cp_wait<1>();          // V_c resident
        __syncthreads();

        // fused exp / probs / E-repack / PV
        #pragma unroll
        for (int j = 0; j < 8; j++) {
            float e0 = __expf(S[j][0]), e1 = __expf(S[j][1]);
            float e2 = __expf(S[j][2]), e3 = __expf(S[j][3]);

            *(float2*)(prowA + c * 128 + half * 64 + 8 * j + 2 * t) = make_float2(e0 * invA, e1 * invA);
            *(float2*)(prowB + c * 128 + half * 64 + 8 * j + 2 * t) = make_float2(e2 * invB, e3 * invB);

            // repack C-frag (n=2t,2t+1) -> tf32 A-frag (k=t, t+4)
            float x0 = __shfl_sync(0xffffffffu, e0, srcl);
            float x1 = __shfl_sync(0xffffffffu, e1, srcl);
            float x2 = __shfl_sync(0xffffffffu, e2, srcl);
            float x3 = __shfl_sync(0xffffffffu, e3, srcl);
            float y0 = __shfl_sync(0xffffffffu, e0, srcl2);
            float y1 = __shfl_sync(0xffffffffu, e1, srcl2);
            float y2 = __shfl_sync(0xffffffffu, e2, srcl2);
            float y3 = __shfl_sync(0xffffffffu, e3, srcl2);
            uint32_t a[4];
            a[0] = f2tf32((t & 1) ? x1 : x0);
            a[1] = f2tf32((t & 1) ? x3 : x2);
            a[2] = f2tf32((t & 1) ? y1 : y0);
            a[3] = f2tf32((t & 1) ? y3 : y2);

            #pragma unroll
            for (int p = 0; p < 4; p++) {
                uint32_t bb[4];
                ldsm_x4(bb, smb + SM_V + (uint32_t)((p * 16 + half * 8 + j) * 512) + ldoff);
                mma_tf32(O[2 * p],     a, bb[0], bb[1]);
                mma_tf32(O[2 * p + 1], a, bb[2], bb[3]);
            }
        }
        __syncthreads();       // done reading V region
        if (c + 1 < NCH) {
            const unsigned char* src = kvb + (size_t)(c + 1) * CH_B + OFF_VT;
            #pragma unroll
            for (int u = 0; u < 8; u++)
                cpa16(smb + SM_V + tid * 16 + u * 4096, src + tid * 16 + u * 4096);
        }
        CP_COMMIT();
    }
    cp_wait<0>();
    __syncthreads();

    // ================= cross-half O reduction + output =================
    {
        float* red = (float*)(sm + SM_K) + wp * 1024;
        if (half == 1) {
            #pragma unroll
            for (int nd = 0; nd < 8; nd++) {
                red[ g      * 64 + nd * 8 + 2 * t]     = O[nd][0];
                red[ g      * 64 + nd * 8 + 2 * t + 1] = O[nd][1];
                red[(g + 8) * 64 + nd * 8 + 2 * t]     = O[nd][2];
                red[(g + 8) * 64 + nd * 8 + 2 * t + 1] = O[nd][3];
            }
        }
        __syncthreads();
        if (half == 0) {
            float* oar0 = out_attn + (((size_t)b * Tn + row0 + g) * Hn + h) * Dn;
            float* oar1 = oar0 + 8 * RS;
            #pragma unroll
            for (int nd = 0; nd < 8; nd++) {
                float o0 = O[nd][0] + red[ g      * 64 + nd * 8 + 2 * t];
                float o1 = O[nd][1] + red[ g      * 64 + nd * 8 + 2 * t + 1];
                float o2 = O[nd][2] + red[(g + 8) * 64 + nd * 8 + 2 * t];
                float o3 = O[nd][3] + red[(g + 8) * 64 + nd * 8 + 2 * t + 1];
                *(float2*)(oar0 + nd * 8 + 2 * t) = make_float2(o0 * invA, o1 * invA);
                *(float2*)(oar1 + nd * 8 + 2 * t) = make_float2(o2 * invB, o3 * invB);
            }
        }
    }
}

extern "C" void kernel_launch(void* const* d_in, const int* in_sizes, int n_in,
                              void* d_out, int out_size) {
    const float* q = (const float*)d_in[0];
    const float* k = (const float*)d_in[1];
    const float* v = (const float*)d_in[2];
    float* out_attn  = (float*)d_out;
    float* out_probs = (float*)d_out + (size_t)Bn * Tn * Hn * Dn;

    cudaFuncSetAttribute(attn_main,
                         cudaFuncAttributeMaxDynamicSharedMemorySize, SMEM_MAIN);

    dim3 pgrid(NCH, Hn, Bn);
    prep_kernel<<<pgrid, 128>>>(k, v);

    dim3 grid(Tn / MQ, Hn, Bn);
    attn_main<<<grid, NT, SMEM_MAIN>>>(q, out_attn, out_probs);
}

// round 8
// speedup vs baseline: 5.5963x; 1.4413x over previous
#include <cuda_runtime.h>
#include <cuda_fp16.h>
#include <cstdint>

#define Bn 4
#define Tn 1024
#define Sn 1024
#define Hn 16
#define Dn 64
#define RS (Hn*Dn)
#define MQ 64
#define NKC 128
#define NCH (Sn/NKC)
#define NT 256

// per-(b,h,chunk) scratch: [K fp16 16KB][V fp16 16KB], swizzled smem-image layout
#define CH_B 32768
#define OFF_KF 0
#define OFF_VF 16384
__device__ __align__(128) unsigned char g_kv[(size_t)Bn*Hn*NCH*CH_B];   // 16 MB

// main-kernel smem: K double buffer at 0/16K, V double buffer at 32K/48K
#define SM_V 32768
#define SM_SUMS 65536
#define SMEM_MAIN 66048

// ---------------- PTX wrappers ----------------
__device__ __forceinline__ uint32_t smem_u32(const void* p) {
    uint32_t a;
    asm("{ .reg .u64 t; cvta.to.shared.u64 t, %1; cvt.u32.u64 %0, t; }" : "=r"(a) : "l"(p));
    return a;
}
__device__ __forceinline__ void ldsm_x4(uint32_t* r, uint32_t addr) {
    asm volatile("ldmatrix.sync.aligned.m8n8.x4.shared.b16 {%0,%1,%2,%3}, [%4];"
        : "=r"(r[0]), "=r"(r[1]), "=r"(r[2]), "=r"(r[3]) : "r"(addr));
}
__device__ __forceinline__ void ldsm_x4_t(uint32_t* r, uint32_t addr) {
    asm volatile("ldmatrix.sync.aligned.m8n8.x4.trans.shared.b16 {%0,%1,%2,%3}, [%4];"
        : "=r"(r[0]), "=r"(r[1]), "=r"(r[2]), "=r"(r[3]) : "r"(addr));
}
__device__ __forceinline__ void mma_f16(float* c, const uint32_t* a, uint32_t b0, uint32_t b1) {
    asm volatile("mma.sync.aligned.m16n8k16.row.col.f32.f16.f16.f32 "
        "{%0,%1,%2,%3}, {%4,%5,%6,%7}, {%8,%9}, {%0,%1,%2,%3};"
        : "+f"(c[0]), "+f"(c[1]), "+f"(c[2]), "+f"(c[3])
        : "r"(a[0]), "r"(a[1]), "r"(a[2]), "r"(a[3]), "r"(b0), "r"(b1));
}
__device__ __forceinline__ void cpa16(uint32_t s, const void* g) {
    asm volatile("cp.async.cg.shared.global [%0], [%1], 16;" :: "r"(s), "l"(g));
}
#define CP_COMMIT() asm volatile("cp.async.commit_group;" ::: "memory")
template<int N> __device__ __forceinline__ void cp_wait() {
    asm volatile("cp.async.wait_group %0;" :: "n"(N) : "memory");
}
__device__ __forceinline__ uint32_t packh2(float a, float b) {
    __half2 h = __floats2half2_rn(a, b);
    return *(uint32_t*)&h;
}

// =================== prep: fp32 K/V -> fp16 swizzled tiles ===================
__global__ __launch_bounds__(128)
void prep_kernel(const float* __restrict__ k, const float* __restrict__ v) {
    const int c = blockIdx.x, h = blockIdx.y, b = blockIdx.z, tid = threadIdx.x;
    const float* kb = k + (((size_t)b * Sn + c * NKC) * Hn + h) * Dn;
    const float* vb = v + (((size_t)b * Sn + c * NKC) * Hn + h) * Dn;
    unsigned char* dst = g_kv + (size_t)((b * Hn + h) * NCH + c) * CH_B;
    #pragma unroll
    for (int u = 0; u < 16; u++) {
        int fid = tid + u * 128;
        int r = fid >> 4, c4 = fid & 15;
        uint32_t so = (uint32_t)(r * 128 + c4 * 8) ^ ((uint32_t)(r & 7) << 4);
        float4 x = *(const float4*)(kb + (size_t)r * RS + c4 * 4);
        *(uint2*)(dst + OFF_KF + so) = make_uint2(packh2(x.x, x.y), packh2(x.z, x.w));
        float4 y = *(const float4*)(vb + (size_t)r * RS + c4 * 4);
        *(uint2*)(dst + OFF_VF + so) = make_uint2(packh2(y.x, y.y), packh2(y.z, y.w));
    }
}

// =================== main attention kernel ===================
__global__ __launch_bounds__(NT, 2)
void attn_main(const float* __restrict__ q,
               float* __restrict__ out_attn, float* __restrict__ out_probs) {
    extern __shared__ char sm[];
    const uint32_t smb = smem_u32(sm);
    const int tid = threadIdx.x, lane = tid & 31, w = tid >> 5;
    const int wp = w & 3, half = w >> 2;          // query band / key half
    const int t0 = blockIdx.x * MQ, h = blockIdx.y, b = blockIdx.z;
    const int g = lane >> 2, t = lane & 3;
    const int row0 = t0 + wp * 16;

    const unsigned char* kvb = g_kv + (size_t)((b * Hn + h) * NCH) * CH_B;
    const float* qr0 = q + (((size_t)b * Tn + row0 + g) * Hn + h) * Dn;
    const float* qr1 = qr0 + 8 * RS;

    // ---- Q fp16 fragments (scale 1/8 folded in), shared by both passes ----
    uint32_t qf[4][4];
    #pragma unroll
    for (int ks = 0; ks < 4; ks++) {
        float2 f0 = *(const float2*)(qr0 + ks * 16 + 2 * t);
        float2 f1 = *(const float2*)(qr1 + ks * 16 + 2 * t);
        float2 f2 = *(const float2*)(qr0 + ks * 16 + 2 * t + 8);
        float2 f3 = *(const float2*)(qr1 + ks * 16 + 2 * t + 8);
        qf[ks][0] = packh2(f0.x * 0.125f, f0.y * 0.125f);
        qf[ks][1] = packh2(f1.x * 0.125f, f1.y * 0.125f);
        qf[ks][2] = packh2(f2.x * 0.125f, f2.y * 0.125f);
        qf[ks][3] = packh2(f3.x * 0.125f, f3.y * 0.125f);
    }

    // ldmatrix lane addressing (within-tile SW128)
    const uint32_t rowoff = ((lane >> 4) & 1) * 8 + (lane & 7);
    const uint32_t colsel = ((lane >> 3) & 1) * 16;
    const uint32_t lbase = rowoff * 128 + colsel;
    const uint32_t lxor = (rowoff & 7) << 4;

    float sumA = 0.f, sumB = 0.f;

    // ================= Pass A: rowsums (fp16 1-term, double-buffered K) =================
    {
        #pragma unroll
        for (int u = 0; u < 4; u++)
            cpa16(smb + tid * 16 + u * 4096, kvb + OFF_KF + tid * 16 + u * 4096);
        CP_COMMIT();
        #pragma unroll
        for (int u = 0; u < 4; u++)
            cpa16(smb + 16384 + tid * 16 + u * 4096, kvb + CH_B + OFF_KF + tid * 16 + u * 4096);
        CP_COMMIT();

        for (int c = 0; c < NCH; c++) {
            cp_wait<1>();
            __syncthreads();
            const uint32_t kb_s = smb + (uint32_t)(c & 1) * 16384;

            float S[8][4];
            #pragma unroll
            for (int i = 0; i < 8; i++) { S[i][0] = 0.f; S[i][1] = 0.f; S[i][2] = 0.f; S[i][3] = 0.f; }
            #pragma unroll
            for (int ks = 0; ks < 4; ks++) {
                #pragma unroll
                for (int j = 0; j < 4; j++) {
                    const int jj = half * 4 + j;
                    uint32_t bh[4];
                    ldsm_x4(bh, (kb_s + jj * 2048 + ks * 32 + lbase) ^ lxor);
                    mma_f16(S[2 * j],     qf[ks], bh[0], bh[1]);
                    mma_f16(S[2 * j + 1], qf[ks], bh[2], bh[3]);
                }
            }
            #pragma unroll
            for (int i = 0; i < 8; i++) {
                sumA += __expf(S[i][0]) + __expf(S[i][1]);
                sumB += __expf(S[i][2]) + __expf(S[i][3]);
            }
            __syncthreads();
            if (c + 2 < NCH) {
                const unsigned char* src = kvb + (size_t)(c + 2) * CH_B + OFF_KF;
                uint32_t d = smb + (uint32_t)(c & 1) * 16384;
                #pragma unroll
                for (int u = 0; u < 4; u++)
                    cpa16(d + tid * 16 + u * 4096, src + tid * 16 + u * 4096);
            }
            CP_COMMIT();
        }
        cp_wait<0>();
        __syncthreads();
    }
    sumA += __shfl_xor_sync(0xffffffffu, sumA, 1);
    sumA += __shfl_xor_sync(0xffffffffu, sumA, 2);
    sumB += __shfl_xor_sync(0xffffffffu, sumB, 1);
    sumB += __shfl_xor_sync(0xffffffffu, sumB, 2);

    // pass B prologue: K0, V0 (double-buffered each)
    #pragma unroll
    for (int u = 0; u < 4; u++)
        cpa16(smb + tid * 16 + u * 4096, kvb + OFF_KF + tid * 16 + u * 4096);
    CP_COMMIT();
    #pragma unroll
    for (int u = 0; u < 4; u++)
        cpa16(smb + SM_V + tid * 16 + u * 4096, kvb + OFF_VF + tid * 16 + u * 4096);
    CP_COMMIT();

    // cross-half rowsum exchange
    {
        float* ss = (float*)(sm + SM_SUMS);
        if (t == 0) { ss[w * 16 + g * 2] = sumA; ss[w * 16 + g * 2 + 1] = sumB; }
        __syncthreads();
        sumA += ss[(w ^ 4) * 16 + g * 2];
        sumB += ss[(w ^ 4) * 16 + g * 2 + 1];
    }
    const float invA = 1.f / sumA, invB = 1.f / sumB;

    // ================= Pass B: probs + PV (fp16 1-term, normalized P) =================
    float O[8][4];
    #pragma unroll
    for (int i = 0; i < 8; i++) { O[i][0] = 0.f; O[i][1] = 0.f; O[i][2] = 0.f; O[i][3] = 0.f; }

    float* prowA = out_probs + (((size_t)b * Tn + row0 + g) * Hn + h) * Sn;
    float* prowB = prowA + (size_t)8 * Hn * Sn;

    for (int c = 0; c < NCH; c++) {
        cp_wait<1>();          // K_c resident
        __syncthreads();
        const uint32_t kb_s = smb + (uint32_t)(c & 1) * 16384;
        const uint32_t vb_s = smb + SM_V + (uint32_t)(c & 1) * 16384;

        float S[8][4];
        #pragma unroll
        for (int i = 0; i < 8; i++) { S[i][0] = 0.f; S[i][1] = 0.f; S[i][2] = 0.f; S[i][3] = 0.f; }
        #pragma unroll
        for (int ks = 0; ks < 4; ks++) {
            #pragma unroll
            for (int j = 0; j < 4; j++) {
                const int jj = half * 4 + j;
                uint32_t bh[4];
                ldsm_x4(bh, (kb_s + jj * 2048 + ks * 32 + lbase) ^ lxor);
                mma_f16(S[2 * j],     qf[ks], bh[0], bh[1]);
                mma_f16(S[2 * j + 1], qf[ks], bh[2], bh[3]);
            }
        }
        // prefetch K_{c+1} into other K buffer (safe: last read in chunk c-1)
        if (c + 1 < NCH) {
            const unsigned char* src = kvb + (size_t)(c + 1) * CH_B + OFF_KF;
            uint32_t d = smb + (uint32_t)((c + 1) & 1) * 16384;
            #pragma unroll
            for (int u = 0; u < 4; u++)
                cpa16(d + tid * 16 + u * 4096, src + tid * 16 + u * 4096);
        }
        CP_COMMIT();
        cp_wait<1>();          // V_c resident
        __syncthreads();

        // fused exp / normalize / probs store / pack / PV
        #pragma unroll
        for (int ks = 0; ks < 4; ks++) {
            const int kk = half * 4 + ks;
            float pa0 = __expf(S[2 * ks][0]) * invA,     pa1 = __expf(S[2 * ks][1]) * invA;
            float pb2 = __expf(S[2 * ks][2]) * invB,     pb3 = __expf(S[2 * ks][3]) * invB;
            float pa4 = __expf(S[2 * ks + 1][0]) * invA, pa5 = __expf(S[2 * ks + 1][1]) * invA;
            float pb6 = __expf(S[2 * ks + 1][2]) * invB, pb7 = __expf(S[2 * ks + 1][3]) * invB;

            *(float2*)(prowA + c * 128 + kk * 16 + 2 * t)     = make_float2(pa0, pa1);
            *(float2*)(prowA + c * 128 + kk * 16 + 8 + 2 * t) = make_float2(pa4, pa5);
            *(float2*)(prowB + c * 128 + kk * 16 + 2 * t)     = make_float2(pb2, pb3);
            *(float2*)(prowB + c * 128 + kk * 16 + 8 + 2 * t) = make_float2(pb6, pb7);

            // C-frag -> fp16 A-frag (FA identity mapping, no shuffles)
            uint32_t a[4];
            a[0] = packh2(pa0, pa1);
            a[1] = packh2(pb2, pb3);
            a[2] = packh2(pa4, pa5);
            a[3] = packh2(pb6, pb7);

            #pragma unroll
            for (int p = 0; p < 4; p++) {
                uint32_t bv[4];
                ldsm_x4_t(bv, (vb_s + kk * 2048 + p * 32 + lbase) ^ lxor);
                mma_f16(O[2 * p],     a, bv[0], bv[2]);
                mma_f16(O[2 * p + 1], a, bv[1], bv[3]);
            }
        }
        // prefetch V_{c+1} into other V buffer
        if (c + 1 < NCH) {
            const unsigned char* src = kvb + (size_t)(c + 1) * CH_B + OFF_VF;
            uint32_t d = smb + SM_V + (uint32_t)((c + 1) & 1) * 16384;
            #pragma unroll
            for (int u = 0; u < 4; u++)
                cpa16(d + tid * 16 + u * 4096, src + tid * 16 + u * 4096);
        }
        CP_COMMIT();
    }
    cp_wait<0>();
    __syncthreads();

    // ================= cross-half O reduction + output (P pre-normalized) =================
    {
        float* red = (float*)sm + wp * 1024;    // 16x64 region per pair
        if (half == 1) {
            #pragma unroll
            for (int nd = 0; nd < 8; nd++) {
                red[ g      * 64 + nd * 8 + 2 * t]     = O[nd][0];
                red[ g      * 64 + nd * 8 + 2 * t + 1] = O[nd][1];
                red[(g + 8) * 64 + nd * 8 + 2 * t]     = O[nd][2];
                red[(g + 8) * 64 + nd * 8 + 2 * t + 1] = O[nd][3];
            }
        }
        __syncthreads();
        if (half == 0) {
            float* oar0 = out_attn + (((size_t)b * Tn + row0 + g) * Hn + h) * Dn;
            float* oar1 = oar0 + 8 * RS;
            #pragma unroll
            for (int nd = 0; nd < 8; nd++) {
                float o0 = O[nd][0] + red[ g      * 64 + nd * 8 + 2 * t];
                float o1 = O[nd][1] + red[ g      * 64 + nd * 8 + 2 * t + 1];
                float o2 = O[nd][2] + red[(g + 8) * 64 + nd * 8 + 2 * t];
                float o3 = O[nd][3] + red[(g + 8) * 64 + nd * 8 + 2 * t + 1];
                *(float2*)(oar0 + nd * 8 + 2 * t) = make_float2(o0, o1);
                *(float2*)(oar1 + nd * 8 + 2 * t) = make_float2(o2, o3);
            }
        }
    }
}

extern "C" void kernel_launch(void* const* d_in, const int* in_sizes, int n_in,
                              void* d_out, int out_size) {
    const float* q = (const float*)d_in[0];
    const float* k = (const float*)d_in[1];
    const float* v = (const float*)d_in[2];
    float* out_attn  = (float*)d_out;
    float* out_probs = (float*)d_out + (size_t)Bn * Tn * Hn * Dn;

    cudaFuncSetAttribute(attn_main,
                         cudaFuncAttributeMaxDynamicSharedMemorySize, SMEM_MAIN);

    dim3 pgrid(NCH, Hn, Bn);
    prep_kernel<<<pgrid, 128>>>(k, v);

    dim3 grid(Tn / MQ, Hn, Bn);
    attn_main<<<grid, NT, SMEM_MAIN>>>(q, out_attn, out_probs);
}

// round 9
// speedup vs baseline: 6.1701x; 1.1025x over previous
#include <cuda_runtime.h>
#include <cuda_fp16.h>
#include <cstdint>

#define Bn 4
#define Tn 1024
#define Sn 1024
#define Hn 16
#define Dn 64
#define RS (Hn*Dn)
#define MQc 128              // queries per CTA
#define NKC 64               // keys per chunk
#define NCH (Sn/NKC)         // 16
#define NT 128

// per-(b,h,chunk) scratch: [K fp16 8KB][V fp16 8KB], swizzled smem-image layout
#define CH_B 16384
#define OFF_K 0
#define OFF_V 8192
__device__ __align__(128) unsigned char g_kv[(size_t)Bn*Hn*NCH*CH_B];   // 16 MB

// smem: K double buffer 0/8K, V double buffer 16K/24K
#define SM_V 16384
#define SMEM_MAIN 32768

// ---------------- PTX wrappers ----------------
__device__ __forceinline__ uint32_t smem_u32(const void* p) {
    uint32_t a;
    asm("{ .reg .u64 t; cvta.to.shared.u64 t, %1; cvt.u32.u64 %0, t; }" : "=r"(a) : "l"(p));
    return a;
}
__device__ __forceinline__ void ldsm_x4(uint32_t* r, uint32_t addr) {
    asm volatile("ldmatrix.sync.aligned.m8n8.x4.shared.b16 {%0,%1,%2,%3}, [%4];"
        : "=r"(r[0]), "=r"(r[1]), "=r"(r[2]), "=r"(r[3]) : "r"(addr));
}
__device__ __forceinline__ void ldsm_x4_t(uint32_t* r, uint32_t addr) {
    asm volatile("ldmatrix.sync.aligned.m8n8.x4.trans.shared.b16 {%0,%1,%2,%3}, [%4];"
        : "=r"(r[0]), "=r"(r[1]), "=r"(r[2]), "=r"(r[3]) : "r"(addr));
}
__device__ __forceinline__ void mma_f16(float* c, const uint32_t* a, uint32_t b0, uint32_t b1) {
    asm volatile("mma.sync.aligned.m16n8k16.row.col.f32.f16.f16.f32 "
        "{%0,%1,%2,%3}, {%4,%5,%6,%7}, {%8,%9}, {%0,%1,%2,%3};"
        : "+f"(c[0]), "+f"(c[1]), "+f"(c[2]), "+f"(c[3])
        : "r"(a[0]), "r"(a[1]), "r"(a[2]), "r"(a[3]), "r"(b0), "r"(b1));
}
__device__ __forceinline__ void cpa16(uint32_t s, const void* g) {
    asm volatile("cp.async.cg.shared.global [%0], [%1], 16;" :: "r"(s), "l"(g));
}
#define CP_COMMIT() asm volatile("cp.async.commit_group;" ::: "memory")
template<int N> __device__ __forceinline__ void cp_wait() {
    asm volatile("cp.async.wait_group %0;" :: "n"(N) : "memory");
}
__device__ __forceinline__ uint32_t packh2(float a, float b) {
    __half2 h = __floats2half2_rn(a, b);
    return *(uint32_t*)&h;
}

// =================== prep: fp32 K/V -> fp16 swizzled 64-key tiles ===================
__global__ __launch_bounds__(128)
void prep_kernel(const float* __restrict__ k, const float* __restrict__ v) {
    const int c = blockIdx.x, h = blockIdx.y, b = blockIdx.z, tid = threadIdx.x;
    const float* kb = k + (((size_t)b * Sn + c * NKC) * Hn + h) * Dn;
    const float* vb = v + (((size_t)b * Sn + c * NKC) * Hn + h) * Dn;
    unsigned char* dst = g_kv + (size_t)((b * Hn + h) * NCH + c) * CH_B;
    #pragma unroll
    for (int u = 0; u < 8; u++) {
        int fid = tid + u * 128;
        int r = fid >> 4, c4 = fid & 15;      // key row 0..63, dim group
        uint32_t so = (uint32_t)(r * 128 + c4 * 8) ^ ((uint32_t)(r & 7) << 4);
        float4 x = *(const float4*)(kb + (size_t)r * RS + c4 * 4);
        *(uint2*)(dst + OFF_K + so) = make_uint2(packh2(x.x, x.y), packh2(x.z, x.w));
        float4 y = *(const float4*)(vb + (size_t)r * RS + c4 * 4);
        *(uint2*)(dst + OFF_V + so) = make_uint2(packh2(y.x, y.y), packh2(y.z, y.w));
    }
}

// =================== main attention kernel ===================
__global__ __launch_bounds__(NT, 3)
void attn_main(const float* __restrict__ q,
               float* __restrict__ out_attn, float* __restrict__ out_probs) {
    extern __shared__ char sm[];
    const uint32_t smb = smem_u32(sm);
    const int tid = threadIdx.x, lane = tid & 31, w = tid >> 5;
    const int band = w * 32;                  // warp owns 32 query rows
    const int t0 = blockIdx.x * MQc, h = blockIdx.y, b = blockIdx.z;
    const int g = lane >> 2, t = lane & 3;

    const unsigned char* kvb = g_kv + (size_t)((b * Hn + h) * NCH) * CH_B;
    const float* qbase = q + (((size_t)b * Tn + t0 + band + g) * Hn + h) * Dn;

    // ---- Q fp16 fragments, 2 m-tiles, scale 1/8 folded in ----
    uint32_t qf[2][4][4];
    #pragma unroll
    for (int m = 0; m < 2; m++) {
        const float* qrG = qbase + (size_t)(m * 16) * RS;
        const float* qrH = qrG + 8 * RS;
        #pragma unroll
        for (int ks = 0; ks < 4; ks++) {
            float2 f0 = *(const float2*)(qrG + ks * 16 + 2 * t);
            float2 f1 = *(const float2*)(qrH + ks * 16 + 2 * t);
            float2 f2 = *(const float2*)(qrG + ks * 16 + 2 * t + 8);
            float2 f3 = *(const float2*)(qrH + ks * 16 + 2 * t + 8);
            qf[m][ks][0] = packh2(f0.x * 0.125f, f0.y * 0.125f);
            qf[m][ks][1] = packh2(f1.x * 0.125f, f1.y * 0.125f);
            qf[m][ks][2] = packh2(f2.x * 0.125f, f2.y * 0.125f);
            qf[m][ks][3] = packh2(f3.x * 0.125f, f3.y * 0.125f);
        }
    }

    // ldmatrix lane addressing (within-tile SW128)
    const uint32_t rowoff = ((lane >> 4) & 1) * 8 + (lane & 7);
    const uint32_t colsel = ((lane >> 3) & 1) * 16;
    const uint32_t lbase = rowoff * 128 + colsel;
    const uint32_t lxor = (rowoff & 7) << 4;

    float sG[2] = {0.f, 0.f}, sH[2] = {0.f, 0.f};

    // ================= Pass A: rowsums (double-buffered 8KB K tiles) =================
    {
        #pragma unroll
        for (int u = 0; u < 4; u++)
            cpa16(smb + tid * 16 + u * 2048, kvb + OFF_K + tid * 16 + u * 2048);
        CP_COMMIT();
        #pragma unroll
        for (int u = 0; u < 4; u++)
            cpa16(smb + 8192 + tid * 16 + u * 2048, kvb + CH_B + OFF_K + tid * 16 + u * 2048);
        CP_COMMIT();

        for (int c = 0; c < NCH; c++) {
            cp_wait<1>();
            __syncthreads();
            const uint32_t kb_s = smb + (uint32_t)(c & 1) * 8192;

            float S[2][8][4];
            #pragma unroll
            for (int m = 0; m < 2; m++)
                #pragma unroll
                for (int i = 0; i < 8; i++)
                    { S[m][i][0] = 0.f; S[m][i][1] = 0.f; S[m][i][2] = 0.f; S[m][i][3] = 0.f; }
            #pragma unroll
            for (int ks = 0; ks < 4; ks++) {
                #pragma unroll
                for (int jj = 0; jj < 4; jj++) {
                    uint32_t bh[4];
                    ldsm_x4(bh, (kb_s + jj * 2048 + ks * 32 + lbase) ^ lxor);
                    mma_f16(S[0][2 * jj],     qf[0][ks], bh[0], bh[1]);
                    mma_f16(S[0][2 * jj + 1], qf[0][ks], bh[2], bh[3]);
                    mma_f16(S[1][2 * jj],     qf[1][ks], bh[0], bh[1]);
                    mma_f16(S[1][2 * jj + 1], qf[1][ks], bh[2], bh[3]);
                }
            }
            #pragma unroll
            for (int m = 0; m < 2; m++)
                #pragma unroll
                for (int i = 0; i < 8; i++) {
                    sG[m] += __expf(S[m][i][0]) + __expf(S[m][i][1]);
                    sH[m] += __expf(S[m][i][2]) + __expf(S[m][i][3]);
                }
            __syncthreads();
            if (c + 2 < NCH) {
                const unsigned char* src = kvb + (size_t)(c + 2) * CH_B + OFF_K;
                uint32_t d = smb + (uint32_t)(c & 1) * 8192;
                #pragma unroll
                for (int u = 0; u < 4; u++)
                    cpa16(d + tid * 16 + u * 2048, src + tid * 16 + u * 2048);
            }
            CP_COMMIT();
        }
        cp_wait<0>();
        __syncthreads();
    }
    #pragma unroll
    for (int m = 0; m < 2; m++) {
        sG[m] += __shfl_xor_sync(0xffffffffu, sG[m], 1);
        sG[m] += __shfl_xor_sync(0xffffffffu, sG[m], 2);
        sH[m] += __shfl_xor_sync(0xffffffffu, sH[m], 1);
        sH[m] += __shfl_xor_sync(0xffffffffu, sH[m], 2);
    }
    const float iG0 = 1.f / sG[0], iH0 = 1.f / sH[0];
    const float iG1 = 1.f / sG[1], iH1 = 1.f / sH[1];

    // pass B prologue: K0 + V0 in one group
    #pragma unroll
    for (int u = 0; u < 4; u++)
        cpa16(smb + tid * 16 + u * 2048, kvb + OFF_K + tid * 16 + u * 2048);
    #pragma unroll
    for (int u = 0; u < 4; u++)
        cpa16(smb + SM_V + tid * 16 + u * 2048, kvb + OFF_V + tid * 16 + u * 2048);
    CP_COMMIT();

    // ================= Pass B: probs + PV (normalized P, no cross-warp epilogue) =================
    float O[2][8][4];
    #pragma unroll
    for (int m = 0; m < 2; m++)
        #pragma unroll
        for (int i = 0; i < 8; i++)
            { O[m][i][0] = 0.f; O[m][i][1] = 0.f; O[m][i][2] = 0.f; O[m][i][3] = 0.f; }

    float* prow0G = out_probs + (((size_t)b * Tn + t0 + band + g) * Hn + h) * Sn;
    float* prow0H = prow0G + (size_t)8 * Hn * Sn;
    float* prow1G = prow0G + (size_t)16 * Hn * Sn;
    float* prow1H = prow0G + (size_t)24 * Hn * Sn;

    for (int c = 0; c < NCH; c++) {
        cp_wait<0>();
        __syncthreads();
        const uint32_t kb_s = smb + (uint32_t)(c & 1) * 8192;
        const uint32_t vb_s = smb + SM_V + (uint32_t)(c & 1) * 8192;

        // prefetch next chunk into alt buffers (safe: sync above drained chunk c-1 readers)
        if (c + 1 < NCH) {
            const unsigned char* src = kvb + (size_t)(c + 1) * CH_B;
            uint32_t dk = smb + (uint32_t)((c + 1) & 1) * 8192;
            uint32_t dv = smb + SM_V + (uint32_t)((c + 1) & 1) * 8192;
            #pragma unroll
            for (int u = 0; u < 4; u++)
                cpa16(dk + tid * 16 + u * 2048, src + OFF_K + tid * 16 + u * 2048);
            #pragma unroll
            for (int u = 0; u < 4; u++)
                cpa16(dv + tid * 16 + u * 2048, src + OFF_V + tid * 16 + u * 2048);
        }
        CP_COMMIT();

        #pragma unroll
        for (int slab = 0; slab < 2; slab++) {
            float S[2][4][4];
            #pragma unroll
            for (int m = 0; m < 2; m++)
                #pragma unroll
                for (int i = 0; i < 4; i++)
                    { S[m][i][0] = 0.f; S[m][i][1] = 0.f; S[m][i][2] = 0.f; S[m][i][3] = 0.f; }

            #pragma unroll
            for (int ks = 0; ks < 4; ks++) {
                #pragma unroll
                for (int j = 0; j < 2; j++) {
                    const int jj = slab * 2 + j;
                    uint32_t bh[4];
                    ldsm_x4(bh, (kb_s + jj * 2048 + ks * 32 + lbase) ^ lxor);
                    mma_f16(S[0][2 * j],     qf[0][ks], bh[0], bh[1]);
                    mma_f16(S[0][2 * j + 1], qf[0][ks], bh[2], bh[3]);
                    mma_f16(S[1][2 * j],     qf[1][ks], bh[0], bh[1]);
                    mma_f16(S[1][2 * j + 1], qf[1][ks], bh[2], bh[3]);
                }
            }

            #pragma unroll
            for (int kp = 0; kp < 2; kp++) {
                const int col = c * 64 + slab * 32 + kp * 16;
                uint32_t a[2][4];
                {   // m-tile 0
                    float g0 = __expf(S[0][2 * kp][0]) * iG0,     g1 = __expf(S[0][2 * kp][1]) * iG0;
                    float h0 = __expf(S[0][2 * kp][2]) * iH0,     h1 = __expf(S[0][2 * kp][3]) * iH0;
                    float g2 = __expf(S[0][2 * kp + 1][0]) * iG0, g3 = __expf(S[0][2 * kp + 1][1]) * iG0;
                    float h2 = __expf(S[0][2 * kp + 1][2]) * iH0, h3 = __expf(S[0][2 * kp + 1][3]) * iH0;
                    *(float2*)(prow0G + col + 2 * t)     = make_float2(g0, g1);
                    *(float2*)(prow0G + col + 8 + 2 * t) = make_float2(g2, g3);
                    *(float2*)(prow0H + col + 2 * t)     = make_float2(h0, h1);
                    *(float2*)(prow0H + col + 8 + 2 * t) = make_float2(h2, h3);
                    a[0][0] = packh2(g0, g1); a[0][1] = packh2(h0, h1);
                    a[0][2] = packh2(g2, g3); a[0][3] = packh2(h2, h3);
                }
                {   // m-tile 1
                    float g0 = __expf(S[1][2 * kp][0]) * iG1,     g1 = __expf(S[1][2 * kp][1]) * iG1;
                    float h0 = __expf(S[1][2 * kp][2]) * iH1,     h1 = __expf(S[1][2 * kp][3]) * iH1;
                    float g2 = __expf(S[1][2 * kp + 1][0]) * iG1, g3 = __expf(S[1][2 * kp + 1][1]) * iG1;
                    float h2 = __expf(S[1][2 * kp + 1][2]) * iH1, h3 = __expf(S[1][2 * kp + 1][3]) * iH1;
                    *(float2*)(prow1G + col + 2 * t)     = make_float2(g0, g1);
                    *(float2*)(prow1G + col + 8 + 2 * t) = make_float2(g2, g3);
                    *(float2*)(prow1H + col + 2 * t)     = make_float2(h0, h1);
                    *(float2*)(prow1H + col + 8 + 2 * t) = make_float2(h2, h3);
                    a[1][0] = packh2(g0, g1); a[1][1] = packh2(h0, h1);
                    a[1][2] = packh2(g2, g3); a[1][3] = packh2(h2, h3);
                }
                const int kg = slab * 2 + kp;
                #pragma unroll
                for (int p = 0; p < 4; p++) {
                    uint32_t bv[4];
                    ldsm_x4_t(bv, (vb_s + kg * 2048 + p * 32 + lbase) ^ lxor);
                    mma_f16(O[0][2 * p],     a[0], bv[0], bv[2]);
                    mma_f16(O[0][2 * p + 1], a[0], bv[1], bv[3]);
                    mma_f16(O[1][2 * p],     a[1], bv[0], bv[2]);
                    mma_f16(O[1][2 * p + 1], a[1], bv[1], bv[3]);
                }
            }
        }
    }

    // ================= output (P pre-normalized; warp owns all keys) =================
    #pragma unroll
    for (int m = 0; m < 2; m++) {
        float* oarG = out_attn + (((size_t)b * Tn + t0 + band + m * 16 + g) * Hn + h) * Dn;
        float* oarH = oarG + 8 * RS;
        #pragma unroll
        for (int nd = 0; nd < 8; nd++) {
            *(float2*)(oarG + nd * 8 + 2 * t) = make_float2(O[m][nd][0], O[m][nd][1]);
            *(float2*)(oarH + nd * 8 + 2 * t) = make_float2(O[m][nd][2], O[m][nd][3]);
        }
    }
}

extern "C" void kernel_launch(void* const* d_in, const int* in_sizes, int n_in,
                              void* d_out, int out_size) {
    const float* q = (const float*)d_in[0];
    const float* k = (const float*)d_in[1];
    const float* v = (const float*)d_in[2];
    float* out_attn  = (float*)d_out;
    float* out_probs = (float*)d_out + (size_t)Bn * Tn * Hn * Dn;

    cudaFuncSetAttribute(attn_main,
                         cudaFuncAttributeMaxDynamicSharedMemorySize, SMEM_MAIN);

    dim3 pgrid(NCH, Hn, Bn);
    prep_kernel<<<pgrid, 128>>>(k, v);

    dim3 grid(Tn / MQc, Hn, Bn);   // 8 x 16 x 4 = 512 CTAs
    attn_main<<<grid, NT, SMEM_MAIN>>>(q, out_attn, out_probs);
}

// round 10
// speedup vs baseline: 6.6751x; 1.0819x over previous
#include <cuda_runtime.h>
#include <cuda_fp16.h>
#include <cstdint>

#define Bn 4
#define Tn 1024
#define Sn 1024
#define Hn 16
#define Dn 64
#define RS (Hn*Dn)
#define MQc 128              // queries per CTA
#define NKC 64               // keys per chunk
#define NCH (Sn/NKC)         // 16
#define NT 128

// per-(b,h,chunk) scratch: [K fp16 8KB][V fp16 8KB], swizzled smem-image layout
#define CH_B 16384
#define OFF_K 0
#define OFF_V 8192
__device__ __align__(128) unsigned char g_kv[(size_t)Bn*Hn*NCH*CH_B];   // 16 MB

// smem: K double buffer 0/8K, V double buffer 16K/24K
#define SM_V 16384
#define SMEM_MAIN 32768

// exp(x) = ex2(x * log2e); fold log2e/8 into Q scale
#define QSCALE 0.18033688011112042f

// ---------------- PTX wrappers ----------------
__device__ __forceinline__ uint32_t smem_u32(const void* p) {
    uint32_t a;
    asm("{ .reg .u64 t; cvta.to.shared.u64 t, %1; cvt.u32.u64 %0, t; }" : "=r"(a) : "l"(p));
    return a;
}
__device__ __forceinline__ void ldsm_x4(uint32_t* r, uint32_t addr) {
    asm volatile("ldmatrix.sync.aligned.m8n8.x4.shared.b16 {%0,%1,%2,%3}, [%4];"
        : "=r"(r[0]), "=r"(r[1]), "=r"(r[2]), "=r"(r[3]) : "r"(addr));
}
__device__ __forceinline__ void ldsm_x4_t(uint32_t* r, uint32_t addr) {
    asm volatile("ldmatrix.sync.aligned.m8n8.x4.trans.shared.b16 {%0,%1,%2,%3}, [%4];"
        : "=r"(r[0]), "=r"(r[1]), "=r"(r[2]), "=r"(r[3]) : "r"(addr));
}
__device__ __forceinline__ void mma_f16(float* c, const uint32_t* a, uint32_t b0, uint32_t b1) {
    asm volatile("mma.sync.aligned.m16n8k16.row.col.f32.f16.f16.f32 "
        "{%0,%1,%2,%3}, {%4,%5,%6,%7}, {%8,%9}, {%0,%1,%2,%3};"
        : "+f"(c[0]), "+f"(c[1]), "+f"(c[2]), "+f"(c[3])
        : "r"(a[0]), "r"(a[1]), "r"(a[2]), "r"(a[3]), "r"(b0), "r"(b1));
}
__device__ __forceinline__ void cpa16(uint32_t s, const void* g) {
    asm volatile("cp.async.cg.shared.global [%0], [%1], 16;" :: "r"(s), "l"(g));
}
#define CP_COMMIT() asm volatile("cp.async.commit_group;" ::: "memory")
template<int N> __device__ __forceinline__ void cp_wait() {
    asm volatile("cp.async.wait_group %0;" :: "n"(N) : "memory");
}
__device__ __forceinline__ uint32_t packh2(float a, float b) {
    __half2 h = __floats2half2_rn(a, b);
    return *(uint32_t*)&h;
}
__device__ __forceinline__ float ex2f(float x) {
    float r;
    asm("ex2.approx.f32 %0, %1;" : "=f"(r) : "f"(x));
    return r;
}

// =================== prep: fp32 K/V -> fp16 swizzled 64-key tiles ===================
__global__ __launch_bounds__(128)
void prep_kernel(const float* __restrict__ k, const float* __restrict__ v) {
    const int c = blockIdx.x, h = blockIdx.y, b = blockIdx.z, tid = threadIdx.x;
    const float* kb = k + (((size_t)b * Sn + c * NKC) * Hn + h) * Dn;
    const float* vb = v + (((size_t)b * Sn + c * NKC) * Hn + h) * Dn;
    unsigned char* dst = g_kv + (size_t)((b * Hn + h) * NCH + c) * CH_B;
    #pragma unroll
    for (int u = 0; u < 8; u++) {
        int fid = tid + u * 128;
        int r = fid >> 4, c4 = fid & 15;
        uint32_t so = (uint32_t)(r * 128 + c4 * 8) ^ ((uint32_t)(r & 7) << 4);
        float4 x = *(const float4*)(kb + (size_t)r * RS + c4 * 4);
        *(uint2*)(dst + OFF_K + so) = make_uint2(packh2(x.x, x.y), packh2(x.z, x.w));
        float4 y = *(const float4*)(vb + (size_t)r * RS + c4 * 4);
        *(uint2*)(dst + OFF_V + so) = make_uint2(packh2(y.x, y.y), packh2(y.z, y.w));
    }
}

// =================== main attention kernel ===================
__global__ __launch_bounds__(NT, 4)
void attn_main(const float* __restrict__ q,
               float* __restrict__ out_attn, float* __restrict__ out_probs) {
    extern __shared__ char sm[];
    const uint32_t smb = smem_u32(sm);
    const int tid = threadIdx.x, lane = tid & 31, w = tid >> 5;
    const int band = w * 32;                  // warp owns 32 query rows
    const int t0 = blockIdx.x * MQc, h = blockIdx.y, b = blockIdx.z;
    const int g = lane >> 2, t = lane & 3;

    const unsigned char* kvb = g_kv + (size_t)((b * Hn + h) * NCH) * CH_B;
    const float* qbase = q + (((size_t)b * Tn + t0 + band + g) * Hn + h) * Dn;

    // ---- Q fp16 fragments, 2 m-tiles, scale (log2e/8) folded in ----
    uint32_t qf[2][4][4];
    #pragma unroll
    for (int m = 0; m < 2; m++) {
        const float* qrG = qbase + (size_t)(m * 16) * RS;
        const float* qrH = qrG + 8 * RS;
        #pragma unroll
        for (int ks = 0; ks < 4; ks++) {
            float2 f0 = *(const float2*)(qrG + ks * 16 + 2 * t);
            float2 f1 = *(const float2*)(qrH + ks * 16 + 2 * t);
            float2 f2 = *(const float2*)(qrG + ks * 16 + 2 * t + 8);
            float2 f3 = *(const float2*)(qrH + ks * 16 + 2 * t + 8);
            qf[m][ks][0] = packh2(f0.x * QSCALE, f0.y * QSCALE);
            qf[m][ks][1] = packh2(f1.x * QSCALE, f1.y * QSCALE);
            qf[m][ks][2] = packh2(f2.x * QSCALE, f2.y * QSCALE);
            qf[m][ks][3] = packh2(f3.x * QSCALE, f3.y * QSCALE);
        }
    }

    // ldmatrix lane addressing (within-tile SW128)
    const uint32_t rowoff = ((lane >> 4) & 1) * 8 + (lane & 7);
    const uint32_t colsel = ((lane >> 3) & 1) * 16;
    const uint32_t lbase = rowoff * 128 + colsel;
    const uint32_t lxor = (rowoff & 7) << 4;

    float sG[2] = {0.f, 0.f}, sH[2] = {0.f, 0.f};

    // ================= Pass A: rowsums (double-buffered 8KB K tiles, 16-key slabs) =================
    {
        #pragma unroll
        for (int u = 0; u < 4; u++)
            cpa16(smb + tid * 16 + u * 2048, kvb + OFF_K + tid * 16 + u * 2048);
        CP_COMMIT();
        #pragma unroll
        for (int u = 0; u < 4; u++)
            cpa16(smb + 8192 + tid * 16 + u * 2048, kvb + CH_B + OFF_K + tid * 16 + u * 2048);
        CP_COMMIT();

        for (int c = 0; c < NCH; c++) {
            cp_wait<1>();
            __syncthreads();
            const uint32_t kb_s = smb + (uint32_t)(c & 1) * 8192;

            #pragma unroll
            for (int jj = 0; jj < 4; jj++) {
                float S[2][2][4];
                #pragma unroll
                for (int m = 0; m < 2; m++)
                    #pragma unroll
                    for (int i = 0; i < 2; i++)
                        { S[m][i][0] = 0.f; S[m][i][1] = 0.f; S[m][i][2] = 0.f; S[m][i][3] = 0.f; }
                #pragma unroll
                for (int ks = 0; ks < 4; ks++) {
                    uint32_t bh[4];
                    ldsm_x4(bh, (kb_s + jj * 2048 + ks * 32 + lbase) ^ lxor);
                    mma_f16(S[0][0], qf[0][ks], bh[0], bh[1]);
                    mma_f16(S[0][1], qf[0][ks], bh[2], bh[3]);
                    mma_f16(S[1][0], qf[1][ks], bh[0], bh[1]);
                    mma_f16(S[1][1], qf[1][ks], bh[2], bh[3]);
                }
                #pragma unroll
                for (int m = 0; m < 2; m++)
                    #pragma unroll
                    for (int i = 0; i < 2; i++) {
                        sG[m] += ex2f(S[m][i][0]) + ex2f(S[m][i][1]);
                        sH[m] += ex2f(S[m][i][2]) + ex2f(S[m][i][3]);
                    }
            }
            __syncthreads();
            if (c + 2 < NCH) {
                const unsigned char* src = kvb + (size_t)(c + 2) * CH_B + OFF_K;
                uint32_t d = smb + (uint32_t)(c & 1) * 8192;
                #pragma unroll
                for (int u = 0; u < 4; u++)
                    cpa16(d + tid * 16 + u * 2048, src + tid * 16 + u * 2048);
            }
            CP_COMMIT();
        }
        cp_wait<0>();
        __syncthreads();
    }
    #pragma unroll
    for (int m = 0; m < 2; m++) {
        sG[m] += __shfl_xor_sync(0xffffffffu, sG[m], 1);
        sG[m] += __shfl_xor_sync(0xffffffffu, sG[m], 2);
        sH[m] += __shfl_xor_sync(0xffffffffu, sH[m], 1);
        sH[m] += __shfl_xor_sync(0xffffffffu, sH[m], 2);
    }
    const float iG0 = 1.f / sG[0], iH0 = 1.f / sH[0];
    const float iG1 = 1.f / sG[1], iH1 = 1.f / sH[1];

    // pass B prologue: K0 + V0 in one group
    #pragma unroll
    for (int u = 0; u < 4; u++)
        cpa16(smb + tid * 16 + u * 2048, kvb + OFF_K + tid * 16 + u * 2048);
    #pragma unroll
    for (int u = 0; u < 4; u++)
        cpa16(smb + SM_V + tid * 16 + u * 2048, kvb + OFF_V + tid * 16 + u * 2048);
    CP_COMMIT();

    // ================= Pass B: probs + PV (16-key groups, normalized P) =================
    float O[2][8][4];
    #pragma unroll
    for (int m = 0; m < 2; m++)
        #pragma unroll
        for (int i = 0; i < 8; i++)
            { O[m][i][0] = 0.f; O[m][i][1] = 0.f; O[m][i][2] = 0.f; O[m][i][3] = 0.f; }

    float* prow0G = out_probs + (((size_t)b * Tn + t0 + band + g) * Hn + h) * Sn;
    float* prow0H = prow0G + (size_t)8 * Hn * Sn;
    float* prow1G = prow0G + (size_t)16 * Hn * Sn;
    float* prow1H = prow0G + (size_t)24 * Hn * Sn;

    for (int c = 0; c < NCH; c++) {
        cp_wait<0>();
        __syncthreads();
        const uint32_t kb_s = smb + (uint32_t)(c & 1) * 8192;
        const uint32_t vb_s = smb + SM_V + (uint32_t)(c & 1) * 8192;

        // prefetch next chunk into alt buffers
        if (c + 1 < NCH) {
            const unsigned char* src = kvb + (size_t)(c + 1) * CH_B;
            uint32_t dk = smb + (uint32_t)((c + 1) & 1) * 8192;
            uint32_t dv = smb + SM_V + (uint32_t)((c + 1) & 1) * 8192;
            #pragma unroll
            for (int u = 0; u < 4; u++)
                cpa16(dk + tid * 16 + u * 2048, src + OFF_K + tid * 16 + u * 2048);
            #pragma unroll
            for (int u = 0; u < 4; u++)
                cpa16(dv + tid * 16 + u * 2048, src + OFF_V + tid * 16 + u * 2048);
        }
        CP_COMMIT();

        #pragma unroll
        for (int jj = 0; jj < 4; jj++) {
            float S[2][2][4];
            #pragma unroll
            for (int m = 0; m < 2; m++)
                #pragma unroll
                for (int i = 0; i < 2; i++)
                    { S[m][i][0] = 0.f; S[m][i][1] = 0.f; S[m][i][2] = 0.f; S[m][i][3] = 0.f; }

            #pragma unroll
            for (int ks = 0; ks < 4; ks++) {
                uint32_t bh[4];
                ldsm_x4(bh, (kb_s + jj * 2048 + ks * 32 + lbase) ^ lxor);
                mma_f16(S[0][0], qf[0][ks], bh[0], bh[1]);
                mma_f16(S[0][1], qf[0][ks], bh[2], bh[3]);
                mma_f16(S[1][0], qf[1][ks], bh[0], bh[1]);
                mma_f16(S[1][1], qf[1][ks], bh[2], bh[3]);
            }

            const int col = c * 64 + jj * 16;
            uint32_t a[2][4];
            {   // m-tile 0
                float g0 = ex2f(S[0][0][0]) * iG0, g1 = ex2f(S[0][0][1]) * iG0;
                float h0 = ex2f(S[0][0][2]) * iH0, h1 = ex2f(S[0][0][3]) * iH0;
                float g2 = ex2f(S[0][1][0]) * iG0, g3 = ex2f(S[0][1][1]) * iG0;
                float h2 = ex2f(S[0][1][2]) * iH0, h3 = ex2f(S[0][1][3]) * iH0;
                __stcs((float2*)(prow0G + col + 2 * t),     make_float2(g0, g1));
                __stcs((float2*)(prow0G + col + 8 + 2 * t), make_float2(g2, g3));
                __stcs((float2*)(prow0H + col + 2 * t),     make_float2(h0, h1));
                __stcs((float2*)(prow0H + col + 8 + 2 * t), make_float2(h2, h3));
                a[0][0] = packh2(g0, g1); a[0][1] = packh2(h0, h1);
                a[0][2] = packh2(g2, g3); a[0][3] = packh2(h2, h3);
            }
            {   // m-tile 1
                float g0 = ex2f(S[1][0][0]) * iG1, g1 = ex2f(S[1][0][1]) * iG1;
                float h0 = ex2f(S[1][0][2]) * iH1, h1 = ex2f(S[1][0][3]) * iH1;
                float g2 = ex2f(S[1][1][0]) * iG1, g3 = ex2f(S[1][1][1]) * iG1;
                float h2 = ex2f(S[1][1][2]) * iH1, h3 = ex2f(S[1][1][3]) * iH1;
                __stcs((float2*)(prow1G + col + 2 * t),     make_float2(g0, g1));
                __stcs((float2*)(prow1G + col + 8 + 2 * t), make_float2(g2, g3));
                __stcs((float2*)(prow1H + col + 2 * t),     make_float2(h0, h1));
                __stcs((float2*)(prow1H + col + 8 + 2 * t), make_float2(h2, h3));
                a[1][0] = packh2(g0, g1); a[1][1] = packh2(h0, h1);
                a[1][2] = packh2(g2, g3); a[1][3] = packh2(h2, h3);
            }

            #pragma unroll
            for (int p = 0; p < 4; p++) {
                uint32_t bv[4];
                ldsm_x4_t(bv, (vb_s + jj * 2048 + p * 32 + lbase) ^ lxor);
                mma_f16(O[0][2 * p],     a[0], bv[0], bv[2]);
                mma_f16(O[0][2 * p + 1], a[0], bv[1], bv[3]);
                mma_f16(O[1][2 * p],     a[1], bv[0], bv[2]);
                mma_f16(O[1][2 * p + 1], a[1], bv[1], bv[3]);
            }
        }
    }

    // ================= output (P pre-normalized; warp owns all keys) =================
    #pragma unroll
    for (int m = 0; m < 2; m++) {
        float* oarG = out_attn + (((size_t)b * Tn + t0 + band + m * 16 + g) * Hn + h) * Dn;
        float* oarH = oarG + 8 * RS;
        #pragma unroll
        for (int nd = 0; nd < 8; nd++) {
            *(float2*)(oarG + nd * 8 + 2 * t) = make_float2(O[m][nd][0], O[m][nd][1]);
            *(float2*)(oarH + nd * 8 + 2 * t) = make_float2(O[m][nd][2], O[m][nd][3]);
        }
    }
}

extern "C" void kernel_launch(void* const* d_in, const int* in_sizes, int n_in,
                              void* d_out, int out_size) {
    const float* q = (const float*)d_in[0];
    const float* k = (const float*)d_in[1];
    const float* v = (const float*)d_in[2];
    float* out_attn  = (float*)d_out;
    float* out_probs = (float*)d_out + (size_t)Bn * Tn * Hn * Dn;

    cudaFuncSetAttribute(attn_main,
                         cudaFuncAttributeMaxDynamicSharedMemorySize, SMEM_MAIN);

    dim3 pgrid(NCH, Hn, Bn);
    prep_kernel<<<pgrid, 128>>>(k, v);

    dim3 grid(Tn / MQc, Hn, Bn);   // 8 x 16 x 4 = 512 CTAs, 4 CTAs/SM -> single wave
    attn_main<<<grid, NT, SMEM_MAIN>>>(q, out_attn, out_probs);
}